// round 15
// baseline (speedup 1.0000x reference)
#include <cuda_runtime.h>
#include <cuda_bf16.h>
#include <cuda_fp16.h>
#include <cstdint>

#define D_MODEL 640
#define NHEADS  4
#define HEADDIM 256
#define DFF     2048
#define NLAYERS 18
#define SEQ     1024
#define VOCAB   262144
#define EMB_SCALE 25.298221281347036f

#define PADR 40

// -------------------- scratch (device globals) ------------------------------
__device__ __align__(256) float g_x[SEQ * D_MODEL];
__device__ __align__(256) float g_tmpd[3 * SEQ * D_MODEL];
__device__ __align__(256) __nv_bfloat16 g_xn2[2 * SEQ * D_MODEL];
__device__ __align__(256) __half g_xnh[SEQ * D_MODEL];
__device__ __align__(256) float g_qkv[3 * SEQ * 1536];
__device__ __align__(256) __nv_bfloat16 g_q2[2 * SEQ * 1024];
__device__ __align__(256) __nv_bfloat16 g_k2[2 * SEQ * 256];
__device__ __align__(256) __nv_bfloat16 g_vt2[2 * HEADDIM * SEQ];
__device__ __align__(256) float g_sc[NHEADS * SEQ * SEQ];
__device__ __align__(256) __nv_bfloat16 g_p2[(long)NHEADS * 2 * SEQ * SEQ];
__device__ __align__(256) __nv_bfloat16 g_ctx2[2 * SEQ * 1024];
__device__ __align__(256) __nv_bfloat16 g_ga2[2 * SEQ * DFF];
__device__ __align__(256) __nv_bfloat16 g_wqkv2[(long)NLAYERS * 2 * 1536 * 640];
__device__ __align__(256) __nv_bfloat16 g_wo2[(long)NLAYERS * 2 * 640 * 1024];
__device__ __align__(256) __nv_bfloat16 g_wgu2[(long)NLAYERS * 2 * 4096 * 640];
__device__ __align__(256) __nv_bfloat16 g_wd2[(long)NLAYERS * 2 * 640 * 2048];
__device__ __align__(256) float g_ropec[2 * SEQ * 128];
__device__ __align__(256) float g_ropes[2 * SEQ * 128];

// -------------------- asm / pack helpers -------------------------------------
__device__ __forceinline__ unsigned smem_u32(const void* p) {
    return (unsigned)__cvta_generic_to_shared(p);
}
__device__ __forceinline__ void cp_async16(void* smem, const void* gmem) {
    asm volatile("cp.async.cg.shared.global [%0], [%1], 16;\n"
                 :: "r"(smem_u32(smem)), "l"(gmem));
}
__device__ __forceinline__ void cp_commit() { asm volatile("cp.async.commit_group;\n"); }
template <int N> __device__ __forceinline__ void cp_wait() {
    asm volatile("cp.async.wait_group %0;\n" :: "n"(N));
}
__device__ __forceinline__ void ldsm_x4(unsigned* r, const void* p) {
    asm volatile("ldmatrix.sync.aligned.m8n8.x4.shared.b16 {%0,%1,%2,%3}, [%4];"
                 : "=r"(r[0]), "=r"(r[1]), "=r"(r[2]), "=r"(r[3]) : "r"(smem_u32(p)));
}
__device__ __forceinline__ void mma_bf16(float* c, const unsigned* a, const unsigned* b) {
    asm volatile(
        "mma.sync.aligned.m16n8k16.row.col.f32.bf16.bf16.f32 "
        "{%0,%1,%2,%3}, {%4,%5,%6,%7}, {%8,%9}, {%0,%1,%2,%3};\n"
        : "+f"(c[0]), "+f"(c[1]), "+f"(c[2]), "+f"(c[3])
        : "r"(a[0]), "r"(a[1]), "r"(a[2]), "r"(a[3]), "r"(b[0]), "r"(b[1]));
}
__device__ __forceinline__ void mma_fp16(float* c, const unsigned* a, const unsigned* b) {
    asm volatile(
        "mma.sync.aligned.m16n8k16.row.col.f32.f16.f16.f32 "
        "{%0,%1,%2,%3}, {%4,%5,%6,%7}, {%8,%9}, {%0,%1,%2,%3};\n"
        : "+f"(c[0]), "+f"(c[1]), "+f"(c[2]), "+f"(c[3])
        : "r"(a[0]), "r"(a[1]), "r"(a[2]), "r"(a[3]), "r"(b[0]), "r"(b[1]));
}
__device__ __forceinline__ void store_split_plane(__nv_bfloat16* p, long ps, float x) {
    __nv_bfloat16 h = __float2bfloat16(x);
    p[0]  = h;
    p[ps] = __float2bfloat16(x - __bfloat162float(h));
}
__device__ __forceinline__ unsigned pack2(__nv_bfloat16 a, __nv_bfloat16 b) {
    __nv_bfloat162 v = __halves2bfloat162(a, b);
    return *reinterpret_cast<unsigned*>(&v);
}
__device__ __forceinline__ void split4(float4 v, uint2& hi, uint2& lo) {
    __nv_bfloat16 h0 = __float2bfloat16(v.x), h1 = __float2bfloat16(v.y);
    __nv_bfloat16 h2 = __float2bfloat16(v.z), h3 = __float2bfloat16(v.w);
    hi.x = pack2(h0, h1); hi.y = pack2(h2, h3);
    lo.x = pack2(__float2bfloat16(v.x - __bfloat162float(h0)),
                 __float2bfloat16(v.y - __bfloat162float(h1)));
    lo.y = pack2(__float2bfloat16(v.z - __bfloat162float(h2)),
                 __float2bfloat16(v.w - __bfloat162float(h3)));
}
__device__ __forceinline__ float gelu_tanh(float g) {
    float u = 0.7978845608028654f * (g + 0.044715f * g * g * g);
    float e = __expf(2.0f * u);
    float th = 1.0f - 2.0f / (e + 1.0f);
    return 0.5f * g * (1.0f + th);
}
// warp-level reductions (all lanes receive result; no barriers)
__device__ __forceinline__ float warp_sum(float v) {
    #pragma unroll
    for (int o = 16; o > 0; o >>= 1) v += __shfl_xor_sync(0xffffffffu, v, o);
    return v;
}
__device__ __forceinline__ float warp_max(float v) {
    #pragma unroll
    for (int o = 16; o > 0; o >>= 1) v = fmaxf(v, __shfl_xor_sync(0xffffffffu, v, o));
    return v;
}

// -------------------- 3-term split bf16 GEMM (BN=64, 3-stage, 1 sync) -------
// EPI: 0 = fp32 out, 1 = split-bf16 out, 2 = fused gelu-mul split out.
template <int EPI>
__global__ void __launch_bounds__(256, 2) gemm3(
    const __nv_bfloat16* __restrict__ A, const __nv_bfloat16* __restrict__ B,
    float* __restrict__ Cf, __nv_bfloat16* __restrict__ Cs,
    int K, int lda, int ldb, long planeA, long planeB,
    int ldc, long planeC,
    long sA, long sB, long sC, int win, int kwin, int kchunk)
{
    constexpr int BN = 64;
    constexpr int STAGE = (256 + 2 * BN) * PADR;
    extern __shared__ __nv_bfloat16 sm[];

    A += (long)blockIdx.z * sA;
    B += (long)blockIdx.z * sB;
    if (EPI == 0) Cf += (long)blockIdx.z * sC; else Cs += (long)blockIdx.z * sC;

    const int m0 = blockIdx.y << 7;
    const int n0 = blockIdx.x * BN;
    if (win > 0) {
        if (n0 > m0 + 127) return;
        if (n0 + BN - 1 < m0 - win + 1) return;
    }
    const int tid = threadIdx.x, lane = tid & 31, warp = tid >> 5;
    const int wm = warp >> 1, wn = warp & 1;
    const int gid = lane >> 2, tig = lane & 3;

    int kbeg = 0, kend = K;
    if (kchunk > 0) {
        kbeg = blockIdx.z * kchunk;
        kend = kbeg + kchunk; if (kend > K) kend = K;
    } else if (kwin > 0) {
        kbeg = m0 - kwin + 1; if (kbeg < 0) kbeg = 0; kbeg &= ~31;
        kend = m0 + 128; if (kend > K) kend = K;
    }
    const int nk = (kend - kbeg) >> 5;

    float acc[2][4][4];
    #pragma unroll
    for (int mt = 0; mt < 2; mt++)
        #pragma unroll
        for (int nt = 0; nt < 4; nt++)
            #pragma unroll
            for (int i = 0; i < 4; i++) acc[mt][nt][i] = 0.0f;

    const __nv_bfloat16* Abase = A + (long)m0 * lda;
    const __nv_bfloat16* Bbase = B + (long)n0 * ldb;

    auto load_tile = [&](int s, int k0) {
        __nv_bfloat16* st = sm + s * STAGE;
        const __nv_bfloat16* Ab = Abase + k0;
        #pragma unroll
        for (int i = 0; i < 2; i++) {
            int idx = tid + (i << 8);
            int r = idx >> 2, c = (idx & 3) << 3;
            cp_async16(st + r * PADR + c, Ab + (long)r * lda + c);
            cp_async16(st + 128 * PADR + r * PADR + c, Ab + planeA + (long)r * lda + c);
        }
        const __nv_bfloat16* Bb = Bbase + k0;
        {
            int r = tid >> 2, c = (tid & 3) << 3;
            cp_async16(st + 256 * PADR + r * PADR + c, Bb + (long)r * ldb + c);
            cp_async16(st + (256 + BN) * PADR + r * PADR + c, Bb + planeB + (long)r * ldb + c);
        }
        cp_commit();
    };

    load_tile(0, kbeg);
    if (nk > 1) load_tile(1, kbeg + 32);

    const int arow = wm * 32 + (lane & 15);
    const int acol = (lane >> 4) << 3;
    const int brow = wn * 32 + ((lane >> 4) << 3) + (lane & 7);
    const int bcol = ((lane >> 3) & 1) << 3;

    for (int kt = 0; kt < nk; kt++) {
        if (kt + 1 < nk) cp_wait<1>(); else cp_wait<0>();
        __syncthreads();
        if (kt + 2 < nk) load_tile((kt + 2) % 3, kbeg + ((kt + 2) << 5));

        const __nv_bfloat16* Ahp = sm + (kt % 3) * STAGE;
        const __nv_bfloat16* Alp = Ahp + 128 * PADR;
        const __nv_bfloat16* Bhp = Ahp + 256 * PADR;
        const __nv_bfloat16* Blp = Ahp + (256 + BN) * PADR;

        #pragma unroll
        for (int kk = 0; kk < 2; kk++) {
            unsigned ah[2][4], al[2][4], bh[2][4], bl[2][4];
            #pragma unroll
            for (int mt = 0; mt < 2; mt++) {
                ldsm_x4(ah[mt], Ahp + (long)(arow + mt * 16) * PADR + kk * 16 + acol);
                ldsm_x4(al[mt], Alp + (long)(arow + mt * 16) * PADR + kk * 16 + acol);
            }
            #pragma unroll
            for (int p = 0; p < 2; p++) {
                ldsm_x4(bh[p], Bhp + (long)(brow + p * 16) * PADR + kk * 16 + bcol);
                ldsm_x4(bl[p], Blp + (long)(brow + p * 16) * PADR + kk * 16 + bcol);
            }
            #pragma unroll
            for (int mt = 0; mt < 2; mt++)
                #pragma unroll
                for (int nt = 0; nt < 4; nt++) {
                    const unsigned* bhf = &bh[nt >> 1][(nt & 1) << 1];
                    const unsigned* blf = &bl[nt >> 1][(nt & 1) << 1];
                    mma_bf16(acc[mt][nt], ah[mt], bhf);
                    mma_bf16(acc[mt][nt], ah[mt], blf);
                    mma_bf16(acc[mt][nt], al[mt], bhf);
                }
        }
    }

    #pragma unroll
    for (int mt = 0; mt < 2; mt++) {
        int r = m0 + wm * 32 + mt * 16 + gid;
        #pragma unroll
        for (int nt = 0; nt < 4; nt++) {
            int cc = n0 + wn * 32 + nt * 8 + tig * 2;
            if (EPI == 0) {
                *reinterpret_cast<float2*>(Cf + (long)r * ldc + cc) =
                    make_float2(acc[mt][nt][0], acc[mt][nt][1]);
                *reinterpret_cast<float2*>(Cf + (long)(r + 8) * ldc + cc) =
                    make_float2(acc[mt][nt][2], acc[mt][nt][3]);
            } else if (EPI == 1) {
                store_split_plane(Cs + (long)r * ldc + cc,           planeC, acc[mt][nt][0]);
                store_split_plane(Cs + (long)r * ldc + cc + 1,       planeC, acc[mt][nt][1]);
                store_split_plane(Cs + (long)(r + 8) * ldc + cc,     planeC, acc[mt][nt][2]);
                store_split_plane(Cs + (long)(r + 8) * ldc + cc + 1, planeC, acc[mt][nt][3]);
            } else {
                int f = cc >> 1;
                store_split_plane(Cs + (long)r * ldc + f, planeC,
                                  gelu_tanh(acc[mt][nt][0]) * acc[mt][nt][1]);
                store_split_plane(Cs + (long)(r + 8) * ldc + f, planeC,
                                  gelu_tanh(acc[mt][nt][2]) * acc[mt][nt][3]);
            }
        }
    }
}

// -------------------- fp16 LM head ------------------------------------------
__global__ void __launch_bounds__(256, 2) lmhead_h(
    const __half* __restrict__ A, const float* __restrict__ Bf, float* __restrict__ C)
{
    constexpr int STAGE = 256 * PADR;
    extern __shared__ __half smh[];

    const int m0 = blockIdx.x << 7;
    const int n0 = blockIdx.y << 7;
    const int tid = threadIdx.x, lane = tid & 31, warp = tid >> 5;
    const int wm = warp >> 1, wn = warp & 1;
    const int gid = lane >> 2, tig = lane & 3;

    float acc[2][8][4];
    #pragma unroll
    for (int mt = 0; mt < 2; mt++)
        #pragma unroll
        for (int nt = 0; nt < 8; nt++)
            #pragma unroll
            for (int i = 0; i < 4; i++) acc[mt][nt][i] = 0.0f;

    const __half* Abase = A + (long)m0 * D_MODEL;

    auto load_tileA = [&](int s, int k0) {
        __half* st = smh + s * STAGE;
        #pragma unroll
        for (int i = 0; i < 2; i++) {
            int idx = tid + (i << 8);
            int r = idx >> 2, c = (idx & 3) << 3;
            cp_async16(st + r * PADR + c, Abase + (long)r * D_MODEL + k0 + c);
        }
        cp_commit();
    };

    float4 breg[4];
    const int br = tid >> 1, bc16 = (tid & 1) << 4;
    auto ldgB = [&](int k0) {
        const float4* bp = reinterpret_cast<const float4*>(
            Bf + (long)(n0 + br) * D_MODEL + k0 + bc16);
        breg[0] = bp[0]; breg[1] = bp[1]; breg[2] = bp[2]; breg[3] = bp[3];
    };
    auto stsB = [&](int s) {
        __half* Bh = smh + s * STAGE + 128 * PADR + br * PADR + bc16;
        #pragma unroll
        for (int q = 0; q < 4; q++) {
            __half2 p0 = __floats2half2_rn(breg[q].x, breg[q].y);
            __half2 p1 = __floats2half2_rn(breg[q].z, breg[q].w);
            uint2 v;
            v.x = *reinterpret_cast<unsigned*>(&p0);
            v.y = *reinterpret_cast<unsigned*>(&p1);
            *reinterpret_cast<uint2*>(Bh + q * 4) = v;
        }
    };

    const int nk = D_MODEL / 32;
    ldgB(0);
    load_tileA(0, 0);
    stsB(0);

    const int arow = wm * 32 + (lane & 15);
    const int acol = (lane >> 4) << 3;
    const int brow = wn * 64 + ((lane >> 4) << 3) + (lane & 7);
    const int bcol = ((lane >> 3) & 1) << 3;

    for (int kt = 0; kt < nk; kt++) {
        const bool pf = (kt + 1 < nk);
        if (pf) {
            ldgB((kt + 1) << 5);
            load_tileA((kt + 1) & 1, (kt + 1) << 5);
            cp_wait<1>();
        } else {
            cp_wait<0>();
        }
        __syncthreads();

        const __half* Ap = smh + (kt & 1) * STAGE;
        const __half* Bp = Ap + 128 * PADR;

        #pragma unroll
        for (int kk = 0; kk < 2; kk++) {
            unsigned a[2][4], b[4][4];
            #pragma unroll
            for (int mt = 0; mt < 2; mt++)
                ldsm_x4(a[mt], Ap + (long)(arow + mt * 16) * PADR + kk * 16 + acol);
            #pragma unroll
            for (int p = 0; p < 4; p++)
                ldsm_x4(b[p], Bp + (long)(brow + p * 16) * PADR + kk * 16 + bcol);
            #pragma unroll
            for (int mt = 0; mt < 2; mt++)
                #pragma unroll
                for (int nt = 0; nt < 8; nt++)
                    mma_fp16(acc[mt][nt], a[mt], &b[nt >> 1][(nt & 1) << 1]);
        }
        if (pf) stsB((kt + 1) & 1);
        __syncthreads();
    }

    #pragma unroll
    for (int mt = 0; mt < 2; mt++) {
        int r = m0 + wm * 32 + mt * 16 + gid;
        #pragma unroll
        for (int nt = 0; nt < 8; nt++) {
            int cc = n0 + wn * 64 + nt * 8 + tig * 2;
            *reinterpret_cast<float2*>(C + (long)r * VOCAB + cc) =
                make_float2(acc[mt][nt][0], acc[mt][nt][1]);
            *reinterpret_cast<float2*>(C + (long)(r + 8) * VOCAB + cc) =
                make_float2(acc[mt][nt][2], acc[mt][nt][3]);
        }
    }
}

// -------------------- merged conversions -------------------------------------
__device__ __forceinline__ void conv_seg(const float* src, __nv_bfloat16* dst,
                                         long planeStride, int n8) {
    for (int i = blockIdx.x * blockDim.x + threadIdx.x; i < n8; i += gridDim.x * blockDim.x) {
        float4 a = reinterpret_cast<const float4*>(src)[2 * i];
        float4 b = reinterpret_cast<const float4*>(src)[2 * i + 1];
        uint2 h0, l0, h1, l1;
        split4(a, h0, l0); split4(b, h1, l1);
        uint4 hv; hv.x = h0.x; hv.y = h0.y; hv.z = h1.x; hv.w = h1.y;
        uint4 lv; lv.x = l0.x; lv.y = l0.y; lv.z = l1.x; lv.w = l1.y;
        *reinterpret_cast<uint4*>(dst + ((long)i << 3)) = hv;
        *reinterpret_cast<uint4*>(dst + planeStride + ((long)i << 3)) = lv;
    }
}
__device__ __forceinline__ void conv_seg_il(const float* src, __nv_bfloat16* dst,
                                            int ro, long planeStride, int nRows) {
    int total = nRows * 80;
    for (int i = blockIdx.x * blockDim.x + threadIdx.x; i < total; i += gridDim.x * blockDim.x) {
        int row = i / 80, c8 = i % 80;
        const float4* s = reinterpret_cast<const float4*>(src + (long)row * 640 + c8 * 8);
        float4 a = s[0], b = s[1];
        uint2 h0, l0, h1, l1;
        split4(a, h0, l0); split4(b, h1, l1);
        uint4 hv; hv.x = h0.x; hv.y = h0.y; hv.z = h1.x; hv.w = h1.y;
        uint4 lv; lv.x = l0.x; lv.y = l0.y; lv.z = l1.x; lv.w = l1.y;
        __nv_bfloat16* d = dst + (long)(2 * row + ro) * 640 + c8 * 8;
        *reinterpret_cast<uint4*>(d) = hv;
        *reinterpret_cast<uint4*>(d + planeStride) = lv;
    }
}
__global__ void conv_all_a(const float* __restrict__ wq, const float* __restrict__ wk,
                           const float* __restrict__ wv, __nv_bfloat16* __restrict__ wqkv2) {
    const long pQKV = (long)1536 * 640;
    int l = blockIdx.z;
    __nv_bfloat16* dst = wqkv2 + (long)l * 2 * pQKV;
    if (blockIdx.y == 0)
        conv_seg(wq + (long)l * 1024 * 640, dst,               pQKV, 1024 * 640 / 8);
    else if (blockIdx.y == 1)
        conv_seg(wk + (long)l *  256 * 640, dst + 1024L * 640, pQKV,  256 * 640 / 8);
    else
        conv_seg(wv + (long)l *  256 * 640, dst + 1280L * 640, pQKV,  256 * 640 / 8);
}
__global__ void conv_all_b(const float* __restrict__ wo, const float* __restrict__ wg,
                           const float* __restrict__ wu, const float* __restrict__ wd,
                           __nv_bfloat16* __restrict__ wo2, __nv_bfloat16* __restrict__ wgu2,
                           __nv_bfloat16* __restrict__ wd2) {
    const long pWO = (long)640 * 1024, pWGU = (long)4096 * 640, pWD = (long)640 * 2048;
    int l = blockIdx.z;
    if (blockIdx.y == 0)
        conv_seg(wo + (long)l * 640 * 1024, wo2 + (long)l * 2 * pWO, pWO, 640 * 1024 / 8);
    else if (blockIdx.y == 1)
        conv_seg_il(wg + (long)l * 2048 * 640, wgu2 + (long)l * 2 * pWGU, 0, pWGU, 2048);
    else if (blockIdx.y == 2)
        conv_seg_il(wu + (long)l * 2048 * 640, wgu2 + (long)l * 2 * pWGU, 1, pWGU, 2048);
    else
        conv_seg(wd + (long)l * 640 * 2048, wd2 + (long)l * 2 * pWD, pWD, 640 * 2048 / 8);
}

// -------------------- rope tables -------------------------------------------
__global__ void rope_table_kernel() {
    int t = blockIdx.x, b = blockIdx.y, d = threadIdx.x;
    float base = b ? 1000000.0f : 10000.0f;
    float invf = powf(base, -((float)d) / 128.0f);
    float s, c;
    sincosf((float)t * invf, &s, &c);
    long idx = ((long)b * SEQ + t) * 128 + d;
    g_ropec[idx] = c;
    g_ropes[idx] = s;
}

// -------------------- warp-per-row elementwise kernels -----------------------
__global__ void embed_kernel(const int* __restrict__ ids, const float* __restrict__ emb,
                             float* __restrict__ x) {
    int t = blockIdx.x;
    long id = (long)ids[t];
    for (int d = threadIdx.x; d < D_MODEL; d += blockDim.x)
        x[(long)t * D_MODEL + d] = emb[id * D_MODEL + d] * EMB_SCALE;
}

// warp w handles row t = blockIdx.x*8 + w.  640 elems = 20/lane. No barriers.
__global__ void __launch_bounds__(256) rmsnorm_split_kernel(
    const float* __restrict__ x, const float* __restrict__ w,
    __nv_bfloat16* __restrict__ o2, long plane) {
    int wp = threadIdx.x >> 5, lane = threadIdx.x & 31;
    int t = (blockIdx.x << 3) + wp;
    const float* row = x + (long)t * D_MODEL;
    float v[20];
    float ss = 0.0f;
    #pragma unroll
    for (int i = 0; i < 20; i++) { v[i] = row[i * 32 + lane]; ss += v[i] * v[i]; }
    ss = warp_sum(ss);
    float scale = rsqrtf(ss / (float)D_MODEL + 1e-6f);
    #pragma unroll
    for (int i = 0; i < 20; i++) {
        int d = i * 32 + lane;
        store_split_plane(o2 + (long)t * D_MODEL + d, plane, v[i] * scale * (1.0f + w[d]));
    }
}

// fused: x += rms(sum of 3 tmp slices, wa); o2 = split(rms(x, wn)); opt fp16 copy
__global__ void __launch_bounds__(256) rmsadd_norm_split(
    float* __restrict__ x, const float* __restrict__ tmp, long tmpSlice,
    const float* __restrict__ wa, const float* __restrict__ wn,
    __nv_bfloat16* __restrict__ o2, long plane, __half* __restrict__ oh) {
    int wp = threadIdx.x >> 5, lane = threadIdx.x & 31;
    int t = (blockIdx.x << 3) + wp;
    float* xr = x + (long)t * D_MODEL;
    const float* tr = tmp + (long)t * D_MODEL;
    float tv[20];
    float ss = 0.0f;
    #pragma unroll
    for (int i = 0; i < 20; i++) {
        int d = i * 32 + lane;
        tv[i] = tr[d] + tr[d + tmpSlice] + tr[d + 2 * tmpSlice];
        ss += tv[i] * tv[i];
    }
    ss = warp_sum(ss);
    float s1 = rsqrtf(ss / (float)D_MODEL + 1e-6f);
    float xv[20];
    ss = 0.0f;
    #pragma unroll
    for (int i = 0; i < 20; i++) {
        int d = i * 32 + lane;
        xv[i] = xr[d] + tv[i] * s1 * (1.0f + wa[d]);
        xr[d] = xv[i];
        ss += xv[i] * xv[i];
    }
    ss = warp_sum(ss);
    float s2 = rsqrtf(ss / (float)D_MODEL + 1e-6f);
    #pragma unroll
    for (int i = 0; i < 20; i++) {
        int d = i * 32 + lane;
        float v = xv[i] * s2 * (1.0f + wn[d]);
        store_split_plane(o2 + (long)t * D_MODEL + d, plane, v);
        if (oh) oh[(long)t * D_MODEL + d] = __float2half(v);
    }
}

// warp per (t, h): grid (SEQ/8, 5), 256 threads. 256-elem rows = 4 pairs/lane.
__global__ void __launch_bounds__(256) qknorm_rope_fused(
    const float* __restrict__ qkv, long dup,
    const float* __restrict__ qw, const float* __restrict__ kw,
    __nv_bfloat16* __restrict__ q2, __nv_bfloat16* __restrict__ k2,
    long pQ, long pK, int bsel) {
    int wp = threadIdx.x >> 5, lane = threadIdx.x & 31;
    int t = (blockIdx.x << 3) + wp;
    int h = blockIdx.y;
    const float* row;
    __nv_bfloat16* orow;
    const float* w;
    long plane;
    if (h < NHEADS) {
        row = qkv + (long)t * 1536 + h * HEADDIM;
        orow = q2 + (long)t * 1024 + h * HEADDIM;
        w = qw; plane = pQ;
    } else {
        row = qkv + (long)t * 1536 + 1024;
        orow = k2 + (long)t * 256;
        w = kw; plane = pK;
    }
    float v1[4], v2[4];
    float ss = 0.0f;
    #pragma unroll
    for (int i = 0; i < 4; i++) {
        int d = i * 32 + lane;
        v1[i] = row[d] + row[d + dup] + row[d + 2 * dup];
        v2[i] = row[d + 128] + row[d + 128 + dup] + row[d + 128 + 2 * dup];
        ss += v1[i] * v1[i] + v2[i] * v2[i];
    }
    ss = warp_sum(ss);
    float scale = rsqrtf(ss / (float)HEADDIM + 1e-6f);
    #pragma unroll
    for (int i = 0; i < 4; i++) {
        int d = i * 32 + lane;
        float q1 = v1[i] * scale * (1.0f + w[d]);
        float q2v = v2[i] * scale * (1.0f + w[d + 128]);
        long ridx = ((long)bsel * SEQ + t) * 128 + d;
        float c = g_ropec[ridx], s = g_ropes[ridx];
        store_split_plane(orow + d,       plane, q1 * c - q2v * s);
        store_split_plane(orow + d + 128, plane, q1 * s + q2v * c);
    }
}

__global__ void transpose_split(const float* __restrict__ in, int rs, long dup,
                                __nv_bfloat16* __restrict__ out, long plane) {
    __shared__ float tile[32][33];
    int r0 = blockIdx.y << 5, c0 = blockIdx.x << 5;
    int x = threadIdx.x, y = threadIdx.y;
    #pragma unroll
    for (int i = 0; i < 32; i += 8) {
        long idx = (long)(r0 + y + i) * rs + c0 + x;
        tile[y + i][x] = in[idx] + in[idx + dup] + in[idx + 2 * dup];
    }
    __syncthreads();
    #pragma unroll
    for (int i = 0; i < 32; i += 8)
        store_split_plane(out + (long)(c0 + y + i) * SEQ + r0 + x, plane, tile[x][y + i]);
}

// warp-per-row softmax: grid (SEQ/8, NHEADS), 256 threads, warp-private buffers
__global__ void __launch_bounds__(256) softmax_split_kernel(
    const float* __restrict__ S, __nv_bfloat16* __restrict__ P, int win) {
    __shared__ float buf[8][1024];
    int wp = threadIdx.x >> 5, lane = threadIdx.x & 31;
    int i = (blockIdx.x << 3) + wp;
    int h = blockIdx.y;
    const float* row = S + ((long)h << 20) + ((long)i << 10);
    __nv_bfloat16* prow = P + (long)h * (2 << 20) + ((long)i << 10);
    const long plane = 1 << 20;
    float* b = buf[wp];
    int lo = i - win + 1; if (lo < 0) lo = 0;
    int m0 = i & ~127;
    int jlo = m0 - win + 1; if (jlo < 0) jlo = 0; jlo &= ~31;
    int jhi = m0 + 128; if (jhi > SEQ) jhi = SEQ;

    float mx = -3.0e38f;
    for (int j = lo + lane; j <= i; j += 32) {
        float v = row[j] * 0.0625f;
        b[j - jlo] = v;
        mx = fmaxf(mx, v);
    }
    mx = warp_max(mx);
    float sum = 0.0f;
    for (int j = lo + lane; j <= i; j += 32) {
        float e = __expf(b[j - jlo] - mx);
        b[j - jlo] = e;
        sum += e;
    }
    sum = warp_sum(sum);
    float inv = 1.0f / sum;
    for (int j = jlo + lane; j < jhi; j += 32) {
        float v = (j >= lo && j <= i) ? b[j - jlo] * inv : 0.0f;
        store_split_plane(prow + j, plane, v);
    }
}

// -------------------- launch ------------------------------------------------
extern "C" void kernel_launch(void* const* d_in, const int* in_sizes, int n_in,
                              void* d_out, int out_size) {
    const int*   input_ids = (const int*)  d_in[0];
    const float* embed     = (const float*)d_in[1];
    const float* ln_in     = (const float*)d_in[2];
    const float* wq        = (const float*)d_in[3];
    const float* wk        = (const float*)d_in[4];
    const float* wv        = (const float*)d_in[5];
    const float* qnw       = (const float*)d_in[6];
    const float* knw       = (const float*)d_in[7];
    const float* wo        = (const float*)d_in[8];
    const float* ln_pa     = (const float*)d_in[9];
    const float* ln_pf     = (const float*)d_in[10];
    const float* wg        = (const float*)d_in[11];
    const float* wu        = (const float*)d_in[12];
    const float* wd        = (const float*)d_in[13];
    const float* ln_ff     = (const float*)d_in[14];
    const float* norm_f    = (const float*)d_in[15];
    float* out = (float*)d_out;

    const int SMEM64  = 3 * (256 + 128) * PADR * 2;
    const int SMEMLMH = 2 * 256 * PADR * 2;
    cudaFuncSetAttribute(gemm3<0>, cudaFuncAttributeMaxDynamicSharedMemorySize, SMEM64);
    cudaFuncSetAttribute(gemm3<1>, cudaFuncAttributeMaxDynamicSharedMemorySize, SMEM64);
    cudaFuncSetAttribute(gemm3<2>, cudaFuncAttributeMaxDynamicSharedMemorySize, SMEM64);
    cudaFuncSetAttribute(lmhead_h, cudaFuncAttributeMaxDynamicSharedMemorySize, SMEMLMH);

    float *x, *tmpd, *qkv, *sc;
    __nv_bfloat16 *xn2, *q2, *k2, *vt2, *p2, *ctx2, *ga2;
    __nv_bfloat16 *wqkv2, *wo2, *wgu2, *wd2;
    __half *xnh;
    cudaGetSymbolAddress((void**)&x,     g_x);
    cudaGetSymbolAddress((void**)&tmpd,  g_tmpd);
    cudaGetSymbolAddress((void**)&xn2,   g_xn2);
    cudaGetSymbolAddress((void**)&xnh,   g_xnh);
    cudaGetSymbolAddress((void**)&qkv,   g_qkv);
    cudaGetSymbolAddress((void**)&q2,    g_q2);
    cudaGetSymbolAddress((void**)&k2,    g_k2);
    cudaGetSymbolAddress((void**)&vt2,   g_vt2);
    cudaGetSymbolAddress((void**)&sc,    g_sc);
    cudaGetSymbolAddress((void**)&p2,    g_p2);
    cudaGetSymbolAddress((void**)&ctx2,  g_ctx2);
    cudaGetSymbolAddress((void**)&ga2,   g_ga2);
    cudaGetSymbolAddress((void**)&wqkv2, g_wqkv2);
    cudaGetSymbolAddress((void**)&wo2,   g_wo2);
    cudaGetSymbolAddress((void**)&wgu2,  g_wgu2);
    cudaGetSymbolAddress((void**)&wd2,   g_wd2);

    const long pXN  = (long)SEQ * D_MODEL;
    const long pQ   = (long)SEQ * 1024;
    const long pK   = (long)SEQ * 256;
    const long pVT  = (long)HEADDIM * SEQ;
    const long pGA  = (long)SEQ * DFF;
    const long QKV_SLICE = (long)SEQ * 1536;

    embed_kernel<<<SEQ, 256>>>(input_ids, embed, x);
    rope_table_kernel<<<dim3(SEQ, 2), 128>>>();
    conv_all_a<<<dim3(320, 3, NLAYERS), 256>>>(wq, wk, wv, wqkv2);
    conv_all_b<<<dim3(640, 4, NLAYERS), 256>>>(wo, wg, wu, wd, wo2, wgu2, wd2);
    rmsnorm_split_kernel<<<SEQ / 8, 256>>>(x, ln_in, xn2, pXN);

    const long pQKV = (long)1536 * 640;
    const long pWO  = (long)640 * 1024;
    const long pWGU = (long)4096 * 640;
    const long pWD  = (long)640 * 2048;

    for (int l = 0; l < NLAYERS; l++) {
        const float* qnw_l   = qnw + l * HEADDIM;
        const float* knw_l   = knw + l * HEADDIM;
        const float* ln_pa_l = ln_pa + l * D_MODEL;
        const float* ln_pf_l = ln_pf + l * D_MODEL;
        const float* ln_ff_l = ln_ff + l * D_MODEL;
        const float* next_w  = (l + 1 < NLAYERS) ? (ln_in + (l + 1) * D_MODEL) : norm_f;
        const __nv_bfloat16* wqkv_l = wqkv2 + (long)l * 2 * pQKV;
        const __nv_bfloat16* wo_l   = wo2   + (long)l * 2 * pWO;
        const __nv_bfloat16* wgu_l  = wgu2  + (long)l * 2 * pWGU;
        const __nv_bfloat16* wd_l   = wd2   + (long)l * 2 * pWD;

        bool is_global = ((l + 1) % 6) == 0;
        int   win  = is_global ? 32768 : 512;
        int   bsel = is_global ? 1 : 0;

        // qkv: split-K x3 -> 576 CTAs
        gemm3<0><<<dim3(24, 8, 3), 256, SMEM64>>>(xn2, wqkv_l, qkv, nullptr,
            640, 640, 640, pXN, pQKV, 1536, 0, 0, 0, QKV_SLICE, -1, -1, 224);
        qknorm_rope_fused<<<dim3(SEQ / 8, NHEADS + 1), 256>>>(qkv, QKV_SLICE, qnw_l, knw_l,
            q2, k2, pQ, pK, bsel);
        transpose_split<<<dim3(8, 32), dim3(32, 8)>>>(qkv + 1280, 1536, QKV_SLICE, vt2, pVT);
        gemm3<0><<<dim3(16, 8, NHEADS), 256, SMEM64>>>(q2, k2, sc, nullptr,
            256, 1024, 256, pQ, pK, 1024, 0, 256, 0, (long)1 << 20, win, -1, 0);
        softmax_split_kernel<<<dim3(SEQ / 8, NHEADS), 256>>>(sc, p2, win);
        // ctx: direct split-bf16 epilogue
        gemm3<1><<<dim3(4, 8, NHEADS), 256, SMEM64>>>(p2, vt2, nullptr, ctx2,
            1024, 1024, 1024, pQ, pVT, 1024, pQ, (long)2 << 20, 0, 256, -1, win, 0);
        // wo: split-K x3 -> 240 CTAs
        gemm3<0><<<dim3(10, 8, 3), 256, SMEM64>>>(ctx2, wo_l, tmpd, nullptr,
            1024, 1024, 1024, pQ, pWO, D_MODEL, 0, 0, 0, pXN, -1, -1, 352);
        rmsadd_norm_split<<<SEQ / 8, 256>>>(x, tmpd, pXN, ln_pa_l, ln_pf_l, xn2, pXN, nullptr);
        gemm3<2><<<dim3(64, 8), 256, SMEM64>>>(xn2, wgu_l, nullptr, ga2,
            640, 640, 640, pXN, pWGU, DFF, pGA, 0, 0, 0, -1, -1, 0);
        // wd: split-K x3 -> 240 CTAs
        gemm3<0><<<dim3(10, 8, 3), 256, SMEM64>>>(ga2, wd_l, tmpd, nullptr,
            2048, 2048, 2048, pGA, pWD, D_MODEL, 0, 0, 0, pXN, -1, -1, 704);
        rmsadd_norm_split<<<SEQ / 8, 256>>>(x, tmpd, pXN, ln_ff_l, next_w, xn2, pXN,
            (l + 1 == NLAYERS) ? xnh : nullptr);
    }

    lmhead_h<<<dim3(8, VOCAB / 128), 256, SMEMLMH>>>(xnh, embed, out);
    (void)in_sizes; (void)n_in; (void)out_size;
}

// round 16
// speedup vs baseline: 1.0177x; 1.0177x over previous
#include <cuda_runtime.h>
#include <cuda_bf16.h>
#include <cuda_fp16.h>
#include <cstdint>

#define D_MODEL 640
#define NHEADS  4
#define HEADDIM 256
#define DFF     2048
#define NLAYERS 18
#define SEQ     1024
#define VOCAB   262144
#define EMB_SCALE 25.298221281347036f

#define PADR 40

// -------------------- scratch (device globals) ------------------------------
__device__ __align__(256) float g_x[SEQ * D_MODEL];
__device__ __align__(256) float g_tmpd[3 * SEQ * D_MODEL];
__device__ __align__(256) __nv_bfloat16 g_xn2[2 * SEQ * D_MODEL];
__device__ __align__(256) __half g_xnh[SEQ * D_MODEL];
__device__ __align__(256) float g_qkv[3 * SEQ * 1536];
__device__ __align__(256) __nv_bfloat16 g_q2[2 * SEQ * 1024];
__device__ __align__(256) __nv_bfloat16 g_k2[2 * SEQ * 256];
__device__ __align__(256) __nv_bfloat16 g_vt2[2 * HEADDIM * SEQ];
__device__ __align__(256) float g_sc[NHEADS * SEQ * SEQ];
__device__ __align__(256) __nv_bfloat16 g_p2[(long)NHEADS * 2 * SEQ * SEQ];
__device__ __align__(256) __nv_bfloat16 g_ctx2[2 * SEQ * 1024];
__device__ __align__(256) __nv_bfloat16 g_ga2[2 * SEQ * DFF];
__device__ __align__(256) __nv_bfloat16 g_wqkv2[(long)NLAYERS * 2 * 1536 * 640];
__device__ __align__(256) __nv_bfloat16 g_wo2[(long)NLAYERS * 2 * 640 * 1024];
__device__ __align__(256) __nv_bfloat16 g_wgu2[(long)NLAYERS * 2 * 4096 * 640];
__device__ __align__(256) __nv_bfloat16 g_wd2[(long)NLAYERS * 2 * 640 * 2048];
__device__ __align__(256) float g_ropec[2 * SEQ * 128];
__device__ __align__(256) float g_ropes[2 * SEQ * 128];

// -------------------- asm / pack helpers -------------------------------------
__device__ __forceinline__ unsigned smem_u32(const void* p) {
    return (unsigned)__cvta_generic_to_shared(p);
}
__device__ __forceinline__ void cp_async16(void* smem, const void* gmem) {
    asm volatile("cp.async.cg.shared.global [%0], [%1], 16;\n"
                 :: "r"(smem_u32(smem)), "l"(gmem));
}
__device__ __forceinline__ void cp_commit() { asm volatile("cp.async.commit_group;\n"); }
template <int N> __device__ __forceinline__ void cp_wait() {
    asm volatile("cp.async.wait_group %0;\n" :: "n"(N));
}
__device__ __forceinline__ void ldsm_x4(unsigned* r, const void* p) {
    asm volatile("ldmatrix.sync.aligned.m8n8.x4.shared.b16 {%0,%1,%2,%3}, [%4];"
                 : "=r"(r[0]), "=r"(r[1]), "=r"(r[2]), "=r"(r[3]) : "r"(smem_u32(p)));
}
__device__ __forceinline__ void mma_bf16(float* c, const unsigned* a, const unsigned* b) {
    asm volatile(
        "mma.sync.aligned.m16n8k16.row.col.f32.bf16.bf16.f32 "
        "{%0,%1,%2,%3}, {%4,%5,%6,%7}, {%8,%9}, {%0,%1,%2,%3};\n"
        : "+f"(c[0]), "+f"(c[1]), "+f"(c[2]), "+f"(c[3])
        : "r"(a[0]), "r"(a[1]), "r"(a[2]), "r"(a[3]), "r"(b[0]), "r"(b[1]));
}
__device__ __forceinline__ void mma_fp16(float* c, const unsigned* a, const unsigned* b) {
    asm volatile(
        "mma.sync.aligned.m16n8k16.row.col.f32.f16.f16.f32 "
        "{%0,%1,%2,%3}, {%4,%5,%6,%7}, {%8,%9}, {%0,%1,%2,%3};\n"
        : "+f"(c[0]), "+f"(c[1]), "+f"(c[2]), "+f"(c[3])
        : "r"(a[0]), "r"(a[1]), "r"(a[2]), "r"(a[3]), "r"(b[0]), "r"(b[1]));
}
__device__ __forceinline__ void store_split_plane(__nv_bfloat16* p, long ps, float x) {
    __nv_bfloat16 h = __float2bfloat16(x);
    p[0]  = h;
    p[ps] = __float2bfloat16(x - __bfloat162float(h));
}
__device__ __forceinline__ unsigned pack2(__nv_bfloat16 a, __nv_bfloat16 b) {
    __nv_bfloat162 v = __halves2bfloat162(a, b);
    return *reinterpret_cast<unsigned*>(&v);
}
__device__ __forceinline__ void split4(float4 v, uint2& hi, uint2& lo) {
    __nv_bfloat16 h0 = __float2bfloat16(v.x), h1 = __float2bfloat16(v.y);
    __nv_bfloat16 h2 = __float2bfloat16(v.z), h3 = __float2bfloat16(v.w);
    hi.x = pack2(h0, h1); hi.y = pack2(h2, h3);
    lo.x = pack2(__float2bfloat16(v.x - __bfloat162float(h0)),
                 __float2bfloat16(v.y - __bfloat162float(h1)));
    lo.y = pack2(__float2bfloat16(v.z - __bfloat162float(h2)),
                 __float2bfloat16(v.w - __bfloat162float(h3)));
}
__device__ __forceinline__ float gelu_tanh(float g) {
    float u = 0.7978845608028654f * (g + 0.044715f * g * g * g);
    float e = __expf(2.0f * u);
    float th = 1.0f - 2.0f / (e + 1.0f);
    return 0.5f * g * (1.0f + th);
}

// -------------------- block reductions (R14 proven forms) -------------------
__device__ __forceinline__ float block_reduce_sum(float v) {
    __shared__ float red[32];
    __syncthreads();
    int lane = threadIdx.x & 31, wid = threadIdx.x >> 5;
    #pragma unroll
    for (int o = 16; o > 0; o >>= 1) v += __shfl_down_sync(0xffffffffu, v, o);
    if (lane == 0) red[wid] = v;
    __syncthreads();
    int nw = (blockDim.x + 31) >> 5;
    v = (threadIdx.x < (unsigned)nw) ? red[threadIdx.x] : 0.0f;
    if (wid == 0) {
        #pragma unroll
        for (int o = 16; o > 0; o >>= 1) v += __shfl_down_sync(0xffffffffu, v, o);
        if (lane == 0) red[0] = v;
    }
    __syncthreads();
    return red[0];
}
__device__ __forceinline__ float block_reduce_max(float v) {
    __shared__ float redm[32];
    __syncthreads();
    int lane = threadIdx.x & 31, wid = threadIdx.x >> 5;
    #pragma unroll
    for (int o = 16; o > 0; o >>= 1) v = fmaxf(v, __shfl_down_sync(0xffffffffu, v, o));
    if (lane == 0) redm[wid] = v;
    __syncthreads();
    int nw = (blockDim.x + 31) >> 5;
    v = (threadIdx.x < (unsigned)nw) ? redm[threadIdx.x] : -3.0e38f;
    if (wid == 0) {
        #pragma unroll
        for (int o = 16; o > 0; o >>= 1) v = fmaxf(v, __shfl_down_sync(0xffffffffu, v, o));
        if (lane == 0) redm[0] = v;
    }
    __syncthreads();
    return redm[0];
}

// -------------------- 3-term split bf16 GEMM (BM template, 3-stage) ---------
// EPI: 0 = fp32 out, 1 = split-bf16 out, 2 = fused gelu-mul split out.
// BM in {64,128}: MT = BM/64 m-fragments per warp.
template <int EPI, int BM>
__global__ void __launch_bounds__(256, 2) gemm3(
    const __nv_bfloat16* __restrict__ A, const __nv_bfloat16* __restrict__ B,
    float* __restrict__ Cf, __nv_bfloat16* __restrict__ Cs,
    int K, int lda, int ldb, long planeA, long planeB,
    int ldc, long planeC,
    long sA, long sB, long sC, int win, int kwin, int kchunk)
{
    constexpr int BN = 64;
    constexpr int MT = BM / 64;
    constexpr int STAGE = (2 * BM + 2 * BN) * PADR;
    extern __shared__ __nv_bfloat16 sm[];

    A += (long)blockIdx.z * sA;
    B += (long)blockIdx.z * sB;
    if (EPI == 0) Cf += (long)blockIdx.z * sC; else Cs += (long)blockIdx.z * sC;

    const int m0 = blockIdx.y * BM;
    const int n0 = blockIdx.x * BN;
    if (win > 0) {
        if (n0 > m0 + BM - 1) return;
        if (n0 + BN - 1 < m0 - win + 1) return;
    }
    const int tid = threadIdx.x, lane = tid & 31, warp = tid >> 5;
    const int wm = warp >> 1, wn = warp & 1;
    const int gid = lane >> 2, tig = lane & 3;

    int kbeg = 0, kend = K;
    if (kchunk > 0) {
        kbeg = blockIdx.z * kchunk;
        kend = kbeg + kchunk; if (kend > K) kend = K;
    } else if (kwin > 0) {
        kbeg = m0 - kwin + 1; if (kbeg < 0) kbeg = 0; kbeg &= ~31;
        kend = m0 + BM; if (kend > K) kend = K;
    }
    const int nk = (kend - kbeg) >> 5;

    float acc[MT][4][4];
    #pragma unroll
    for (int mt = 0; mt < MT; mt++)
        #pragma unroll
        for (int nt = 0; nt < 4; nt++)
            #pragma unroll
            for (int i = 0; i < 4; i++) acc[mt][nt][i] = 0.0f;

    const __nv_bfloat16* Abase = A + (long)m0 * lda;
    const __nv_bfloat16* Bbase = B + (long)n0 * ldb;

    auto load_tile = [&](int s, int k0) {
        __nv_bfloat16* st = sm + s * STAGE;
        const __nv_bfloat16* Ab = Abase + k0;
        #pragma unroll
        for (int i = 0; i < MT; i++) {
            int idx = tid + (i << 8);
            int r = idx >> 2, c = (idx & 3) << 3;
            cp_async16(st + r * PADR + c, Ab + (long)r * lda + c);
            cp_async16(st + BM * PADR + r * PADR + c, Ab + planeA + (long)r * lda + c);
        }
        const __nv_bfloat16* Bb = Bbase + k0;
        {
            int r = tid >> 2, c = (tid & 3) << 3;
            cp_async16(st + 2 * BM * PADR + r * PADR + c, Bb + (long)r * ldb + c);
            cp_async16(st + (2 * BM + BN) * PADR + r * PADR + c,
                       Bb + planeB + (long)r * ldb + c);
        }
        cp_commit();
    };

    load_tile(0, kbeg);
    if (nk > 1) load_tile(1, kbeg + 32);

    const int arow = wm * (16 * MT) + (lane & 15);
    const int acol = (lane >> 4) << 3;
    const int brow = wn * 32 + ((lane >> 4) << 3) + (lane & 7);
    const int bcol = ((lane >> 3) & 1) << 3;

    for (int kt = 0; kt < nk; kt++) {
        if (kt + 1 < nk) cp_wait<1>(); else cp_wait<0>();
        __syncthreads();
        if (kt + 2 < nk) load_tile((kt + 2) % 3, kbeg + ((kt + 2) << 5));

        const __nv_bfloat16* Ahp = sm + (kt % 3) * STAGE;
        const __nv_bfloat16* Alp = Ahp + BM * PADR;
        const __nv_bfloat16* Bhp = Ahp + 2 * BM * PADR;
        const __nv_bfloat16* Blp = Ahp + (2 * BM + BN) * PADR;

        #pragma unroll
        for (int kk = 0; kk < 2; kk++) {
            unsigned ah[MT][4], al[MT][4], bh[2][4], bl[2][4];
            #pragma unroll
            for (int mt = 0; mt < MT; mt++) {
                ldsm_x4(ah[mt], Ahp + (long)(arow + mt * 16) * PADR + kk * 16 + acol);
                ldsm_x4(al[mt], Alp + (long)(arow + mt * 16) * PADR + kk * 16 + acol);
            }
            #pragma unroll
            for (int p = 0; p < 2; p++) {
                ldsm_x4(bh[p], Bhp + (long)(brow + p * 16) * PADR + kk * 16 + bcol);
                ldsm_x4(bl[p], Blp + (long)(brow + p * 16) * PADR + kk * 16 + bcol);
            }
            #pragma unroll
            for (int mt = 0; mt < MT; mt++)
                #pragma unroll
                for (int nt = 0; nt < 4; nt++) {
                    const unsigned* bhf = &bh[nt >> 1][(nt & 1) << 1];
                    const unsigned* blf = &bl[nt >> 1][(nt & 1) << 1];
                    mma_bf16(acc[mt][nt], ah[mt], bhf);
                    mma_bf16(acc[mt][nt], ah[mt], blf);
                    mma_bf16(acc[mt][nt], al[mt], bhf);
                }
        }
    }

    #pragma unroll
    for (int mt = 0; mt < MT; mt++) {
        int r = m0 + wm * (16 * MT) + mt * 16 + gid;
        #pragma unroll
        for (int nt = 0; nt < 4; nt++) {
            int cc = n0 + wn * 32 + nt * 8 + tig * 2;
            if (EPI == 0) {
                *reinterpret_cast<float2*>(Cf + (long)r * ldc + cc) =
                    make_float2(acc[mt][nt][0], acc[mt][nt][1]);
                *reinterpret_cast<float2*>(Cf + (long)(r + 8) * ldc + cc) =
                    make_float2(acc[mt][nt][2], acc[mt][nt][3]);
            } else if (EPI == 1) {
                store_split_plane(Cs + (long)r * ldc + cc,           planeC, acc[mt][nt][0]);
                store_split_plane(Cs + (long)r * ldc + cc + 1,       planeC, acc[mt][nt][1]);
                store_split_plane(Cs + (long)(r + 8) * ldc + cc,     planeC, acc[mt][nt][2]);
                store_split_plane(Cs + (long)(r + 8) * ldc + cc + 1, planeC, acc[mt][nt][3]);
            } else {
                int f = cc >> 1;
                store_split_plane(Cs + (long)r * ldc + f, planeC,
                                  gelu_tanh(acc[mt][nt][0]) * acc[mt][nt][1]);
                store_split_plane(Cs + (long)(r + 8) * ldc + f, planeC,
                                  gelu_tanh(acc[mt][nt][2]) * acc[mt][nt][3]);
            }
        }
    }
}

// -------------------- fp16 LM head ------------------------------------------
__global__ void __launch_bounds__(256, 2) lmhead_h(
    const __half* __restrict__ A, const float* __restrict__ Bf, float* __restrict__ C)
{
    constexpr int STAGE = 256 * PADR;
    extern __shared__ __half smh[];

    const int m0 = blockIdx.x << 7;
    const int n0 = blockIdx.y << 7;
    const int tid = threadIdx.x, lane = tid & 31, warp = tid >> 5;
    const int wm = warp >> 1, wn = warp & 1;
    const int gid = lane >> 2, tig = lane & 3;

    float acc[2][8][4];
    #pragma unroll
    for (int mt = 0; mt < 2; mt++)
        #pragma unroll
        for (int nt = 0; nt < 8; nt++)
            #pragma unroll
            for (int i = 0; i < 4; i++) acc[mt][nt][i] = 0.0f;

    const __half* Abase = A + (long)m0 * D_MODEL;

    auto load_tileA = [&](int s, int k0) {
        __half* st = smh + s * STAGE;
        #pragma unroll
        for (int i = 0; i < 2; i++) {
            int idx = tid + (i << 8);
            int r = idx >> 2, c = (idx & 3) << 3;
            cp_async16(st + r * PADR + c, Abase + (long)r * D_MODEL + k0 + c);
        }
        cp_commit();
    };

    float4 breg[4];
    const int br = tid >> 1, bc16 = (tid & 1) << 4;
    auto ldgB = [&](int k0) {
        const float4* bp = reinterpret_cast<const float4*>(
            Bf + (long)(n0 + br) * D_MODEL + k0 + bc16);
        breg[0] = bp[0]; breg[1] = bp[1]; breg[2] = bp[2]; breg[3] = bp[3];
    };
    auto stsB = [&](int s) {
        __half* Bh = smh + s * STAGE + 128 * PADR + br * PADR + bc16;
        #pragma unroll
        for (int q = 0; q < 4; q++) {
            __half2 p0 = __floats2half2_rn(breg[q].x, breg[q].y);
            __half2 p1 = __floats2half2_rn(breg[q].z, breg[q].w);
            uint2 v;
            v.x = *reinterpret_cast<unsigned*>(&p0);
            v.y = *reinterpret_cast<unsigned*>(&p1);
            *reinterpret_cast<uint2*>(Bh + q * 4) = v;
        }
    };

    const int nk = D_MODEL / 32;
    ldgB(0);
    load_tileA(0, 0);
    stsB(0);

    const int arow = wm * 32 + (lane & 15);
    const int acol = (lane >> 4) << 3;
    const int brow = wn * 64 + ((lane >> 4) << 3) + (lane & 7);
    const int bcol = ((lane >> 3) & 1) << 3;

    for (int kt = 0; kt < nk; kt++) {
        const bool pf = (kt + 1 < nk);
        if (pf) {
            ldgB((kt + 1) << 5);
            load_tileA((kt + 1) & 1, (kt + 1) << 5);
            cp_wait<1>();
        } else {
            cp_wait<0>();
        }
        __syncthreads();

        const __half* Ap = smh + (kt & 1) * STAGE;
        const __half* Bp = Ap + 128 * PADR;

        #pragma unroll
        for (int kk = 0; kk < 2; kk++) {
            unsigned a[2][4], b[4][4];
            #pragma unroll
            for (int mt = 0; mt < 2; mt++)
                ldsm_x4(a[mt], Ap + (long)(arow + mt * 16) * PADR + kk * 16 + acol);
            #pragma unroll
            for (int p = 0; p < 4; p++)
                ldsm_x4(b[p], Bp + (long)(brow + p * 16) * PADR + kk * 16 + bcol);
            #pragma unroll
            for (int mt = 0; mt < 2; mt++)
                #pragma unroll
                for (int nt = 0; nt < 8; nt++)
                    mma_fp16(acc[mt][nt], a[mt], &b[nt >> 1][(nt & 1) << 1]);
        }
        if (pf) stsB((kt + 1) & 1);
        __syncthreads();
    }

    #pragma unroll
    for (int mt = 0; mt < 2; mt++) {
        int r = m0 + wm * 32 + mt * 16 + gid;
        #pragma unroll
        for (int nt = 0; nt < 8; nt++) {
            int cc = n0 + wn * 64 + nt * 8 + tig * 2;
            *reinterpret_cast<float2*>(C + (long)r * VOCAB + cc) =
                make_float2(acc[mt][nt][0], acc[mt][nt][1]);
            *reinterpret_cast<float2*>(C + (long)(r + 8) * VOCAB + cc) =
                make_float2(acc[mt][nt][2], acc[mt][nt][3]);
        }
    }
}

// -------------------- merged conversions -------------------------------------
__device__ __forceinline__ void conv_seg(const float* src, __nv_bfloat16* dst,
                                         long planeStride, int n8) {
    for (int i = blockIdx.x * blockDim.x + threadIdx.x; i < n8; i += gridDim.x * blockDim.x) {
        float4 a = reinterpret_cast<const float4*>(src)[2 * i];
        float4 b = reinterpret_cast<const float4*>(src)[2 * i + 1];
        uint2 h0, l0, h1, l1;
        split4(a, h0, l0); split4(b, h1, l1);
        uint4 hv; hv.x = h0.x; hv.y = h0.y; hv.z = h1.x; hv.w = h1.y;
        uint4 lv; lv.x = l0.x; lv.y = l0.y; lv.z = l1.x; lv.w = l1.y;
        *reinterpret_cast<uint4*>(dst + ((long)i << 3)) = hv;
        *reinterpret_cast<uint4*>(dst + planeStride + ((long)i << 3)) = lv;
    }
}
__device__ __forceinline__ void conv_seg_il(const float* src, __nv_bfloat16* dst,
                                            int ro, long planeStride, int nRows) {
    int total = nRows * 80;
    for (int i = blockIdx.x * blockDim.x + threadIdx.x; i < total; i += gridDim.x * blockDim.x) {
        int row = i / 80, c8 = i % 80;
        const float4* s = reinterpret_cast<const float4*>(src + (long)row * 640 + c8 * 8);
        float4 a = s[0], b = s[1];
        uint2 h0, l0, h1, l1;
        split4(a, h0, l0); split4(b, h1, l1);
        uint4 hv; hv.x = h0.x; hv.y = h0.y; hv.z = h1.x; hv.w = h1.y;
        uint4 lv; lv.x = l0.x; lv.y = l0.y; lv.z = l1.x; lv.w = l1.y;
        __nv_bfloat16* d = dst + (long)(2 * row + ro) * 640 + c8 * 8;
        *reinterpret_cast<uint4*>(d) = hv;
        *reinterpret_cast<uint4*>(d + planeStride) = lv;
    }
}
__global__ void conv_all_a(const float* __restrict__ wq, const float* __restrict__ wk,
                           const float* __restrict__ wv, __nv_bfloat16* __restrict__ wqkv2) {
    const long pQKV = (long)1536 * 640;
    int l = blockIdx.z;
    __nv_bfloat16* dst = wqkv2 + (long)l * 2 * pQKV;
    if (blockIdx.y == 0)
        conv_seg(wq + (long)l * 1024 * 640, dst,               pQKV, 1024 * 640 / 8);
    else if (blockIdx.y == 1)
        conv_seg(wk + (long)l *  256 * 640, dst + 1024L * 640, pQKV,  256 * 640 / 8);
    else
        conv_seg(wv + (long)l *  256 * 640, dst + 1280L * 640, pQKV,  256 * 640 / 8);
}
__global__ void conv_all_b(const float* __restrict__ wo, const float* __restrict__ wg,
                           const float* __restrict__ wu, const float* __restrict__ wd,
                           __nv_bfloat16* __restrict__ wo2, __nv_bfloat16* __restrict__ wgu2,
                           __nv_bfloat16* __restrict__ wd2) {
    const long pWO = (long)640 * 1024, pWGU = (long)4096 * 640, pWD = (long)640 * 2048;
    int l = blockIdx.z;
    if (blockIdx.y == 0)
        conv_seg(wo + (long)l * 640 * 1024, wo2 + (long)l * 2 * pWO, pWO, 640 * 1024 / 8);
    else if (blockIdx.y == 1)
        conv_seg_il(wg + (long)l * 2048 * 640, wgu2 + (long)l * 2 * pWGU, 0, pWGU, 2048);
    else if (blockIdx.y == 2)
        conv_seg_il(wu + (long)l * 2048 * 640, wgu2 + (long)l * 2 * pWGU, 1, pWGU, 2048);
    else
        conv_seg(wd + (long)l * 640 * 2048, wd2 + (long)l * 2 * pWD, pWD, 640 * 2048 / 8);
}

// -------------------- rope tables -------------------------------------------
__global__ void rope_table_kernel() {
    int t = blockIdx.x, b = blockIdx.y, d = threadIdx.x;
    float base = b ? 1000000.0f : 10000.0f;
    float invf = powf(base, -((float)d) / 128.0f);
    float s, c;
    sincosf((float)t * invf, &s, &c);
    long idx = ((long)b * SEQ + t) * 128 + d;
    g_ropec[idx] = c;
    g_ropes[idx] = s;
}

// -------------------- elementwise / norm kernels (R14 block-per-row) --------
__global__ void embed_kernel(const int* __restrict__ ids, const float* __restrict__ emb,
                             float* __restrict__ x) {
    int t = blockIdx.x;
    long id = (long)ids[t];
    for (int d = threadIdx.x; d < D_MODEL; d += blockDim.x)
        x[(long)t * D_MODEL + d] = emb[id * D_MODEL + d] * EMB_SCALE;
}

__global__ void rmsnorm_split_kernel(const float* __restrict__ x, const float* __restrict__ w,
                                     __nv_bfloat16* __restrict__ o2, long plane) {
    int t = blockIdx.x;
    const float* row = x + (long)t * D_MODEL;
    float ss = 0.0f;
    for (int d = threadIdx.x; d < D_MODEL; d += blockDim.x) { float v = row[d]; ss += v * v; }
    ss = block_reduce_sum(ss);
    float scale = rsqrtf(ss / (float)D_MODEL + 1e-6f);
    for (int d = threadIdx.x; d < D_MODEL; d += blockDim.x)
        store_split_plane(o2 + (long)t * D_MODEL + d, plane, row[d] * scale * (1.0f + w[d]));
}

__global__ void rmsadd_norm_split(float* __restrict__ x, const float* __restrict__ tmp,
                                  long tmpSlice,
                                  const float* __restrict__ wa, const float* __restrict__ wn,
                                  __nv_bfloat16* __restrict__ o2, long plane,
                                  __half* __restrict__ oh) {
    int t = blockIdx.x, tid = threadIdx.x;
    float* xr = x + (long)t * D_MODEL;
    const float* tr  = tmp + (long)t * D_MODEL;
    float tv[3];
    float ss = 0.0f;
    #pragma unroll
    for (int i = 0; i < 3; i++) {
        int d = tid + (i << 8);
        if (d < D_MODEL) {
            tv[i] = tr[d] + tr[d + tmpSlice] + tr[d + 2 * tmpSlice];
            ss += tv[i] * tv[i];
        }
    }
    ss = block_reduce_sum(ss);
    float s1 = rsqrtf(ss / (float)D_MODEL + 1e-6f);
    float xv[3];
    ss = 0.0f;
    #pragma unroll
    for (int i = 0; i < 3; i++) {
        int d = tid + (i << 8);
        if (d < D_MODEL) {
            xv[i] = xr[d] + tv[i] * s1 * (1.0f + wa[d]);
            xr[d] = xv[i];
            ss += xv[i] * xv[i];
        }
    }
    ss = block_reduce_sum(ss);
    float s2 = rsqrtf(ss / (float)D_MODEL + 1e-6f);
    #pragma unroll
    for (int i = 0; i < 3; i++) {
        int d = tid + (i << 8);
        if (d < D_MODEL) {
            float v = xv[i] * s2 * (1.0f + wn[d]);
            store_split_plane(o2 + (long)t * D_MODEL + d, plane, v);
            if (oh) oh[(long)t * D_MODEL + d] = __float2half(v);
        }
    }
}

__global__ void qknorm_rope_fused(const float* __restrict__ qkv, long dup,
                                  const float* __restrict__ qw, const float* __restrict__ kw,
                                  __nv_bfloat16* __restrict__ q2, __nv_bfloat16* __restrict__ k2,
                                  long pQ, long pK, int bsel) {
    int t = blockIdx.x, h = blockIdx.y, d = threadIdx.x;
    const float* row;
    __nv_bfloat16* orow;
    const float* w;
    long plane;
    if (h < NHEADS) {
        row = qkv + (long)t * 1536 + h * HEADDIM;
        orow = q2 + (long)t * 1024 + h * HEADDIM;
        w = qw; plane = pQ;
    } else {
        row = qkv + (long)t * 1536 + 1024;
        orow = k2 + (long)t * 256;
        w = kw; plane = pK;
    }
    float v1 = row[d] + row[d + dup] + row[d + 2 * dup];
    float v2 = row[d + 128] + row[d + 128 + dup] + row[d + 128 + 2 * dup];
    float ss = block_reduce_sum(v1 * v1 + v2 * v2);
    float scale = rsqrtf(ss / (float)HEADDIM + 1e-6f);
    float q1 = v1 * scale * (1.0f + w[d]);
    float q2v = v2 * scale * (1.0f + w[d + 128]);
    long ridx = ((long)bsel * SEQ + t) * 128 + d;
    float c = g_ropec[ridx], s = g_ropes[ridx];
    store_split_plane(orow + d,       plane, q1 * c - q2v * s);
    store_split_plane(orow + d + 128, plane, q1 * s + q2v * c);
}

__global__ void transpose_split(const float* __restrict__ in, int rs, long dup,
                                __nv_bfloat16* __restrict__ out, long plane) {
    __shared__ float tile[32][33];
    int r0 = blockIdx.y << 5, c0 = blockIdx.x << 5;
    int x = threadIdx.x, y = threadIdx.y;
    #pragma unroll
    for (int i = 0; i < 32; i += 8) {
        long idx = (long)(r0 + y + i) * rs + c0 + x;
        tile[y + i][x] = in[idx] + in[idx + dup] + in[idx + 2 * dup];
    }
    __syncthreads();
    #pragma unroll
    for (int i = 0; i < 32; i += 8)
        store_split_plane(out + (long)(c0 + y + i) * SEQ + r0 + x, plane, tile[x][y + i]);
}

__global__ void softmax_split_kernel(const float* __restrict__ S,
                                     __nv_bfloat16* __restrict__ P, int win) {
    __shared__ float buf[1024];
    int i = blockIdx.x, h = blockIdx.y;
    const float* row = S + ((long)h << 20) + ((long)i << 10);
    __nv_bfloat16* prow = P + (long)h * (2 << 20) + ((long)i << 10);
    const long plane = 1 << 20;
    int lo = i - win + 1; if (lo < 0) lo = 0;
    int m0 = i & ~127;
    int jlo = m0 - win + 1; if (jlo < 0) jlo = 0; jlo &= ~31;
    int jhi = m0 + 128; if (jhi > SEQ) jhi = SEQ;

    float mx = -3.0e38f;
    for (int j = lo + threadIdx.x; j <= i; j += blockDim.x) {
        float v = row[j] * 0.0625f;
        buf[j - jlo] = v;
        mx = fmaxf(mx, v);
    }
    mx = block_reduce_max(mx);
    float sum = 0.0f;
    for (int j = lo + threadIdx.x; j <= i; j += blockDim.x) {
        float e = __expf(buf[j - jlo] - mx);
        buf[j - jlo] = e;
        sum += e;
    }
    sum = block_reduce_sum(sum);
    float inv = 1.0f / sum;
    for (int j = jlo + threadIdx.x; j < jhi; j += blockDim.x) {
        float v = (j >= lo && j <= i) ? buf[j - jlo] * inv : 0.0f;
        store_split_plane(prow + j, plane, v);
    }
}

// -------------------- launch ------------------------------------------------
extern "C" void kernel_launch(void* const* d_in, const int* in_sizes, int n_in,
                              void* d_out, int out_size) {
    const int*   input_ids = (const int*)  d_in[0];
    const float* embed     = (const float*)d_in[1];
    const float* ln_in     = (const float*)d_in[2];
    const float* wq        = (const float*)d_in[3];
    const float* wk        = (const float*)d_in[4];
    const float* wv        = (const float*)d_in[5];
    const float* qnw       = (const float*)d_in[6];
    const float* knw       = (const float*)d_in[7];
    const float* wo        = (const float*)d_in[8];
    const float* ln_pa     = (const float*)d_in[9];
    const float* ln_pf     = (const float*)d_in[10];
    const float* wg        = (const float*)d_in[11];
    const float* wu        = (const float*)d_in[12];
    const float* wd        = (const float*)d_in[13];
    const float* ln_ff     = (const float*)d_in[14];
    const float* norm_f    = (const float*)d_in[15];
    float* out = (float*)d_out;

    const int SMEM128 = 3 * (256 + 128) * PADR * 2;   // BM=128 stages
    const int SMEM64B = 3 * (128 + 128) * PADR * 2;   // BM=64 stages
    const int SMEMLMH = 2 * 256 * PADR * 2;
    cudaFuncSetAttribute(gemm3<0, 128>, cudaFuncAttributeMaxDynamicSharedMemorySize, SMEM128);
    cudaFuncSetAttribute(gemm3<1, 64>,  cudaFuncAttributeMaxDynamicSharedMemorySize, SMEM64B);
    cudaFuncSetAttribute(gemm3<2, 128>, cudaFuncAttributeMaxDynamicSharedMemorySize, SMEM128);
    cudaFuncSetAttribute(lmhead_h,      cudaFuncAttributeMaxDynamicSharedMemorySize, SMEMLMH);

    float *x, *tmpd, *qkv, *sc;
    __nv_bfloat16 *xn2, *q2, *k2, *vt2, *p2, *ctx2, *ga2;
    __nv_bfloat16 *wqkv2, *wo2, *wgu2, *wd2;
    __half *xnh;
    cudaGetSymbolAddress((void**)&x,     g_x);
    cudaGetSymbolAddress((void**)&tmpd,  g_tmpd);
    cudaGetSymbolAddress((void**)&xn2,   g_xn2);
    cudaGetSymbolAddress((void**)&xnh,   g_xnh);
    cudaGetSymbolAddress((void**)&qkv,   g_qkv);
    cudaGetSymbolAddress((void**)&q2,    g_q2);
    cudaGetSymbolAddress((void**)&k2,    g_k2);
    cudaGetSymbolAddress((void**)&vt2,   g_vt2);
    cudaGetSymbolAddress((void**)&sc,    g_sc);
    cudaGetSymbolAddress((void**)&p2,    g_p2);
    cudaGetSymbolAddress((void**)&ctx2,  g_ctx2);
    cudaGetSymbolAddress((void**)&ga2,   g_ga2);
    cudaGetSymbolAddress((void**)&wqkv2, g_wqkv2);
    cudaGetSymbolAddress((void**)&wo2,   g_wo2);
    cudaGetSymbolAddress((void**)&wgu2,  g_wgu2);
    cudaGetSymbolAddress((void**)&wd2,   g_wd2);

    const long pXN  = (long)SEQ * D_MODEL;
    const long pQ   = (long)SEQ * 1024;
    const long pK   = (long)SEQ * 256;
    const long pVT  = (long)HEADDIM * SEQ;
    const long pGA  = (long)SEQ * DFF;
    const long QKV_SLICE = (long)SEQ * 1536;

    embed_kernel<<<SEQ, 256>>>(input_ids, embed, x);
    rope_table_kernel<<<dim3(SEQ, 2), 128>>>();
    conv_all_a<<<dim3(320, 3, NLAYERS), 256>>>(wq, wk, wv, wqkv2);
    conv_all_b<<<dim3(640, 4, NLAYERS), 256>>>(wo, wg, wu, wd, wo2, wgu2, wd2);
    rmsnorm_split_kernel<<<SEQ, 256>>>(x, ln_in, xn2, pXN);

    const long pQKV = (long)1536 * 640;
    const long pWO  = (long)640 * 1024;
    const long pWGU = (long)4096 * 640;
    const long pWD  = (long)640 * 2048;

    for (int l = 0; l < NLAYERS; l++) {
        const float* qnw_l   = qnw + l * HEADDIM;
        const float* knw_l   = knw + l * HEADDIM;
        const float* ln_pa_l = ln_pa + l * D_MODEL;
        const float* ln_pf_l = ln_pf + l * D_MODEL;
        const float* ln_ff_l = ln_ff + l * D_MODEL;
        const float* next_w  = (l + 1 < NLAYERS) ? (ln_in + (l + 1) * D_MODEL) : norm_f;
        const __nv_bfloat16* wqkv_l = wqkv2 + (long)l * 2 * pQKV;
        const __nv_bfloat16* wo_l   = wo2   + (long)l * 2 * pWO;
        const __nv_bfloat16* wgu_l  = wgu2  + (long)l * 2 * pWGU;
        const __nv_bfloat16* wd_l   = wd2   + (long)l * 2 * pWD;

        bool is_global = ((l + 1) % 6) == 0;
        int   win  = is_global ? 32768 : 512;
        int   bsel = is_global ? 1 : 0;

        // qkv: split-K x3 -> 576 CTAs
        gemm3<0, 128><<<dim3(24, 8, 3), 256, SMEM128>>>(xn2, wqkv_l, qkv, nullptr,
            640, 640, 640, pXN, pQKV, 1536, 0, 0, 0, QKV_SLICE, -1, -1, 224);
        qknorm_rope_fused<<<dim3(SEQ, NHEADS + 1), 128>>>(qkv, QKV_SLICE, qnw_l, knw_l,
            q2, k2, pQ, pK, bsel);
        transpose_split<<<dim3(8, 32), dim3(32, 8)>>>(qkv + 1280, 1536, QKV_SLICE, vt2, pVT);
        gemm3<0, 128><<<dim3(16, 8, NHEADS), 256, SMEM128>>>(q2, k2, sc, nullptr,
            256, 1024, 256, pQ, pK, 1024, 0, 256, 0, (long)1 << 20, win, -1, 0);
        softmax_split_kernel<<<dim3(SEQ, NHEADS), 256>>>(sc, p2, win);
        // ctx: BM=64 -> 256 CTAs, half per-CTA work, no combine
        gemm3<1, 64><<<dim3(4, 16, NHEADS), 256, SMEM64B>>>(p2, vt2, nullptr, ctx2,
            1024, 1024, 1024, pQ, pVT, 1024, pQ, (long)2 << 20, 0, 256, -1, win, 0);
        // wo: split-K x3 -> 240 CTAs
        gemm3<0, 128><<<dim3(10, 8, 3), 256, SMEM128>>>(ctx2, wo_l, tmpd, nullptr,
            1024, 1024, 1024, pQ, pWO, D_MODEL, 0, 0, 0, pXN, -1, -1, 352);
        rmsadd_norm_split<<<SEQ, 256>>>(x, tmpd, pXN, ln_pa_l, ln_pf_l, xn2, pXN, nullptr);
        gemm3<2, 128><<<dim3(64, 8), 256, SMEM128>>>(xn2, wgu_l, nullptr, ga2,
            640, 640, 640, pXN, pWGU, DFF, pGA, 0, 0, 0, -1, -1, 0);
        // wd: split-K x3 -> 240 CTAs
        gemm3<0, 128><<<dim3(10, 8, 3), 256, SMEM128>>>(ga2, wd_l, tmpd, nullptr,
            2048, 2048, 2048, pGA, pWD, D_MODEL, 0, 0, 0, pXN, -1, -1, 704);
        rmsadd_norm_split<<<SEQ, 256>>>(x, tmpd, pXN, ln_ff_l, next_w, xn2, pXN,
            (l + 1 == NLAYERS) ? xnh : nullptr);
    }

    lmhead_h<<<dim3(8, VOCAB / 128), 256, SMEMLMH>>>(xnh, embed, out);
    (void)in_sizes; (void)n_in; (void)out_size;
}

// round 17
// speedup vs baseline: 1.0256x; 1.0078x over previous
#include <cuda_runtime.h>
#include <cuda_bf16.h>
#include <cuda_fp16.h>
#include <cstdint>

#define D_MODEL 640
#define NHEADS  4
#define HEADDIM 256
#define DFF     2048
#define NLAYERS 18
#define SEQ     1024
#define VOCAB   262144
#define EMB_SCALE 25.298221281347036f

#define PADR 40

// -------------------- scratch (device globals) ------------------------------
__device__ __align__(256) float g_x[SEQ * D_MODEL];
__device__ __align__(256) float g_tmpd[3 * SEQ * D_MODEL];
__device__ __align__(256) __nv_bfloat16 g_xn2[2 * SEQ * D_MODEL];
__device__ __align__(256) __half g_xnh[SEQ * D_MODEL];
__device__ __align__(256) float g_qkv[3 * SEQ * 1536];
__device__ __align__(256) __nv_bfloat16 g_q2[2 * SEQ * 1024];
__device__ __align__(256) __nv_bfloat16 g_k2[2 * SEQ * 256];
__device__ __align__(256) __nv_bfloat16 g_vt2[2 * HEADDIM * SEQ];
__device__ __align__(256) float g_sc[NHEADS * SEQ * SEQ];
__device__ __align__(256) __nv_bfloat16 g_p2[(long)NHEADS * 2 * SEQ * SEQ];
__device__ __align__(256) __nv_bfloat16 g_ctx2[2 * SEQ * 1024];
__device__ __align__(256) __nv_bfloat16 g_ga2[2 * SEQ * DFF];
__device__ __align__(256) __nv_bfloat16 g_wqkv2[(long)NLAYERS * 2 * 1536 * 640];
__device__ __align__(256) __nv_bfloat16 g_wo2[(long)NLAYERS * 2 * 640 * 1024];
__device__ __align__(256) __nv_bfloat16 g_wgu2[(long)NLAYERS * 2 * 4096 * 640];
__device__ __align__(256) __nv_bfloat16 g_wd2[(long)NLAYERS * 2 * 640 * 2048];
__device__ __align__(256) float g_ropec[2 * SEQ * 128];
__device__ __align__(256) float g_ropes[2 * SEQ * 128];

// -------------------- asm / pack helpers -------------------------------------
__device__ __forceinline__ unsigned smem_u32(const void* p) {
    return (unsigned)__cvta_generic_to_shared(p);
}
__device__ __forceinline__ void cp_async16(void* smem, const void* gmem) {
    asm volatile("cp.async.cg.shared.global [%0], [%1], 16;\n"
                 :: "r"(smem_u32(smem)), "l"(gmem));
}
__device__ __forceinline__ void cp_commit() { asm volatile("cp.async.commit_group;\n"); }
template <int N> __device__ __forceinline__ void cp_wait() {
    asm volatile("cp.async.wait_group %0;\n" :: "n"(N));
}
__device__ __forceinline__ void ldsm_x4(unsigned* r, const void* p) {
    asm volatile("ldmatrix.sync.aligned.m8n8.x4.shared.b16 {%0,%1,%2,%3}, [%4];"
                 : "=r"(r[0]), "=r"(r[1]), "=r"(r[2]), "=r"(r[3]) : "r"(smem_u32(p)));
}
__device__ __forceinline__ void mma_bf16(float* c, const unsigned* a, const unsigned* b) {
    asm volatile(
        "mma.sync.aligned.m16n8k16.row.col.f32.bf16.bf16.f32 "
        "{%0,%1,%2,%3}, {%4,%5,%6,%7}, {%8,%9}, {%0,%1,%2,%3};\n"
        : "+f"(c[0]), "+f"(c[1]), "+f"(c[2]), "+f"(c[3])
        : "r"(a[0]), "r"(a[1]), "r"(a[2]), "r"(a[3]), "r"(b[0]), "r"(b[1]));
}
__device__ __forceinline__ void mma_fp16(float* c, const unsigned* a, const unsigned* b) {
    asm volatile(
        "mma.sync.aligned.m16n8k16.row.col.f32.f16.f16.f32 "
        "{%0,%1,%2,%3}, {%4,%5,%6,%7}, {%8,%9}, {%0,%1,%2,%3};\n"
        : "+f"(c[0]), "+f"(c[1]), "+f"(c[2]), "+f"(c[3])
        : "r"(a[0]), "r"(a[1]), "r"(a[2]), "r"(a[3]), "r"(b[0]), "r"(b[1]));
}
__device__ __forceinline__ void store_split_plane(__nv_bfloat16* p, long ps, float x) {
    __nv_bfloat16 h = __float2bfloat16(x);
    p[0]  = h;
    p[ps] = __float2bfloat16(x - __bfloat162float(h));
}
__device__ __forceinline__ unsigned pack2(__nv_bfloat16 a, __nv_bfloat16 b) {
    __nv_bfloat162 v = __halves2bfloat162(a, b);
    return *reinterpret_cast<unsigned*>(&v);
}
__device__ __forceinline__ void split4(float4 v, uint2& hi, uint2& lo) {
    __nv_bfloat16 h0 = __float2bfloat16(v.x), h1 = __float2bfloat16(v.y);
    __nv_bfloat16 h2 = __float2bfloat16(v.z), h3 = __float2bfloat16(v.w);
    hi.x = pack2(h0, h1); hi.y = pack2(h2, h3);
    lo.x = pack2(__float2bfloat16(v.x - __bfloat162float(h0)),
                 __float2bfloat16(v.y - __bfloat162float(h1)));
    lo.y = pack2(__float2bfloat16(v.z - __bfloat162float(h2)),
                 __float2bfloat16(v.w - __bfloat162float(h3)));
}
__device__ __forceinline__ float gelu_tanh(float g) {
    float u = 0.7978845608028654f * (g + 0.044715f * g * g * g);
    float e = __expf(2.0f * u);
    float th = 1.0f - 2.0f / (e + 1.0f);
    return 0.5f * g * (1.0f + th);
}

// -------------------- block reductions ---------------------------------------
__device__ __forceinline__ float block_reduce_sum(float v) {
    __shared__ float red[32];
    __syncthreads();
    int lane = threadIdx.x & 31, wid = threadIdx.x >> 5;
    #pragma unroll
    for (int o = 16; o > 0; o >>= 1) v += __shfl_down_sync(0xffffffffu, v, o);
    if (lane == 0) red[wid] = v;
    __syncthreads();
    int nw = (blockDim.x + 31) >> 5;
    v = (threadIdx.x < (unsigned)nw) ? red[threadIdx.x] : 0.0f;
    if (wid == 0) {
        #pragma unroll
        for (int o = 16; o > 0; o >>= 1) v += __shfl_down_sync(0xffffffffu, v, o);
        if (lane == 0) red[0] = v;
    }
    __syncthreads();
    return red[0];
}
__device__ __forceinline__ float block_reduce_max(float v) {
    __shared__ float redm[32];
    __syncthreads();
    int lane = threadIdx.x & 31, wid = threadIdx.x >> 5;
    #pragma unroll
    for (int o = 16; o > 0; o >>= 1) v = fmaxf(v, __shfl_down_sync(0xffffffffu, v, o));
    if (lane == 0) redm[wid] = v;
    __syncthreads();
    int nw = (blockDim.x + 31) >> 5;
    v = (threadIdx.x < (unsigned)nw) ? redm[threadIdx.x] : -3.0e38f;
    if (wid == 0) {
        #pragma unroll
        for (int o = 16; o > 0; o >>= 1) v = fmaxf(v, __shfl_down_sync(0xffffffffu, v, o));
        if (lane == 0) redm[0] = v;
    }
    __syncthreads();
    return redm[0];
}

// -------------------- 3-term split bf16 GEMM (BM template, 3-stage) ---------
// EPI: 0 = fp32 out, 1 = split-bf16 out, 2 = fused gelu-mul split out.
// BM=64 runs 3 CTAs/SM (smaller regs/smem); BM=128 runs 2.
template <int EPI, int BM>
__global__ void __launch_bounds__(256, (BM == 64) ? 3 : 2) gemm3(
    const __nv_bfloat16* __restrict__ A, const __nv_bfloat16* __restrict__ B,
    float* __restrict__ Cf, __nv_bfloat16* __restrict__ Cs,
    int K, int lda, int ldb, long planeA, long planeB,
    int ldc, long planeC,
    long sA, long sB, long sC, int win, int kwin, int kchunk)
{
    constexpr int BN = 64;
    constexpr int MT = BM / 64;
    constexpr int STAGE = (2 * BM + 2 * BN) * PADR;
    extern __shared__ __nv_bfloat16 sm[];

    A += (long)blockIdx.z * sA;
    B += (long)blockIdx.z * sB;
    if (EPI == 0) Cf += (long)blockIdx.z * sC; else Cs += (long)blockIdx.z * sC;

    const int m0 = blockIdx.y * BM;
    const int n0 = blockIdx.x * BN;
    if (win > 0) {
        if (n0 > m0 + BM - 1) return;
        if (n0 + BN - 1 < m0 - win + 1) return;
    }
    const int tid = threadIdx.x, lane = tid & 31, warp = tid >> 5;
    const int wm = warp >> 1, wn = warp & 1;
    const int gid = lane >> 2, tig = lane & 3;

    int kbeg = 0, kend = K;
    if (kchunk > 0) {
        kbeg = blockIdx.z * kchunk;
        kend = kbeg + kchunk; if (kend > K) kend = K;
    } else if (kwin > 0) {
        kbeg = m0 - kwin + 1; if (kbeg < 0) kbeg = 0; kbeg &= ~31;
        kend = m0 + BM; if (kend > K) kend = K;
    }
    const int nk = (kend - kbeg) >> 5;

    float acc[MT][4][4];
    #pragma unroll
    for (int mt = 0; mt < MT; mt++)
        #pragma unroll
        for (int nt = 0; nt < 4; nt++)
            #pragma unroll
            for (int i = 0; i < 4; i++) acc[mt][nt][i] = 0.0f;

    const __nv_bfloat16* Abase = A + (long)m0 * lda;
    const __nv_bfloat16* Bbase = B + (long)n0 * ldb;

    auto load_tile = [&](int s, int k0) {
        __nv_bfloat16* st = sm + s * STAGE;
        const __nv_bfloat16* Ab = Abase + k0;
        #pragma unroll
        for (int i = 0; i < MT; i++) {
            int idx = tid + (i << 8);
            int r = idx >> 2, c = (idx & 3) << 3;
            cp_async16(st + r * PADR + c, Ab + (long)r * lda + c);
            cp_async16(st + BM * PADR + r * PADR + c, Ab + planeA + (long)r * lda + c);
        }
        const __nv_bfloat16* Bb = Bbase + k0;
        {
            int r = tid >> 2, c = (tid & 3) << 3;
            cp_async16(st + 2 * BM * PADR + r * PADR + c, Bb + (long)r * ldb + c);
            cp_async16(st + (2 * BM + BN) * PADR + r * PADR + c,
                       Bb + planeB + (long)r * ldb + c);
        }
        cp_commit();
    };

    load_tile(0, kbeg);
    if (nk > 1) load_tile(1, kbeg + 32);

    const int arow = wm * (16 * MT) + (lane & 15);
    const int acol = (lane >> 4) << 3;
    const int brow = wn * 32 + ((lane >> 4) << 3) + (lane & 7);
    const int bcol = ((lane >> 3) & 1) << 3;

    for (int kt = 0; kt < nk; kt++) {
        if (kt + 1 < nk) cp_wait<1>(); else cp_wait<0>();
        __syncthreads();
        if (kt + 2 < nk) load_tile((kt + 2) % 3, kbeg + ((kt + 2) << 5));

        const __nv_bfloat16* Ahp = sm + (kt % 3) * STAGE;
        const __nv_bfloat16* Alp = Ahp + BM * PADR;
        const __nv_bfloat16* Bhp = Ahp + 2 * BM * PADR;
        const __nv_bfloat16* Blp = Ahp + (2 * BM + BN) * PADR;

        #pragma unroll
        for (int kk = 0; kk < 2; kk++) {
            unsigned ah[MT][4], al[MT][4], bh[2][4], bl[2][4];
            #pragma unroll
            for (int mt = 0; mt < MT; mt++) {
                ldsm_x4(ah[mt], Ahp + (long)(arow + mt * 16) * PADR + kk * 16 + acol);
                ldsm_x4(al[mt], Alp + (long)(arow + mt * 16) * PADR + kk * 16 + acol);
            }
            #pragma unroll
            for (int p = 0; p < 2; p++) {
                ldsm_x4(bh[p], Bhp + (long)(brow + p * 16) * PADR + kk * 16 + bcol);
                ldsm_x4(bl[p], Blp + (long)(brow + p * 16) * PADR + kk * 16 + bcol);
            }
            #pragma unroll
            for (int mt = 0; mt < MT; mt++)
                #pragma unroll
                for (int nt = 0; nt < 4; nt++) {
                    const unsigned* bhf = &bh[nt >> 1][(nt & 1) << 1];
                    const unsigned* blf = &bl[nt >> 1][(nt & 1) << 1];
                    mma_bf16(acc[mt][nt], ah[mt], bhf);
                    mma_bf16(acc[mt][nt], ah[mt], blf);
                    mma_bf16(acc[mt][nt], al[mt], bhf);
                }
        }
    }

    #pragma unroll
    for (int mt = 0; mt < MT; mt++) {
        int r = m0 + wm * (16 * MT) + mt * 16 + gid;
        #pragma unroll
        for (int nt = 0; nt < 4; nt++) {
            int cc = n0 + wn * 32 + nt * 8 + tig * 2;
            if (EPI == 0) {
                *reinterpret_cast<float2*>(Cf + (long)r * ldc + cc) =
                    make_float2(acc[mt][nt][0], acc[mt][nt][1]);
                *reinterpret_cast<float2*>(Cf + (long)(r + 8) * ldc + cc) =
                    make_float2(acc[mt][nt][2], acc[mt][nt][3]);
            } else if (EPI == 1) {
                store_split_plane(Cs + (long)r * ldc + cc,           planeC, acc[mt][nt][0]);
                store_split_plane(Cs + (long)r * ldc + cc + 1,       planeC, acc[mt][nt][1]);
                store_split_plane(Cs + (long)(r + 8) * ldc + cc,     planeC, acc[mt][nt][2]);
                store_split_plane(Cs + (long)(r + 8) * ldc + cc + 1, planeC, acc[mt][nt][3]);
            } else {
                int f = cc >> 1;
                store_split_plane(Cs + (long)r * ldc + f, planeC,
                                  gelu_tanh(acc[mt][nt][0]) * acc[mt][nt][1]);
                store_split_plane(Cs + (long)(r + 8) * ldc + f, planeC,
                                  gelu_tanh(acc[mt][nt][2]) * acc[mt][nt][3]);
            }
        }
    }
}

// -------------------- fp16 LM head ------------------------------------------
__global__ void __launch_bounds__(256, 2) lmhead_h(
    const __half* __restrict__ A, const float* __restrict__ Bf, float* __restrict__ C)
{
    constexpr int STAGE = 256 * PADR;
    extern __shared__ __half smh[];

    const int m0 = blockIdx.x << 7;
    const int n0 = blockIdx.y << 7;
    const int tid = threadIdx.x, lane = tid & 31, warp = tid >> 5;
    const int wm = warp >> 1, wn = warp & 1;
    const int gid = lane >> 2, tig = lane & 3;

    float acc[2][8][4];
    #pragma unroll
    for (int mt = 0; mt < 2; mt++)
        #pragma unroll
        for (int nt = 0; nt < 8; nt++)
            #pragma unroll
            for (int i = 0; i < 4; i++) acc[mt][nt][i] = 0.0f;

    const __half* Abase = A + (long)m0 * D_MODEL;

    auto load_tileA = [&](int s, int k0) {
        __half* st = smh + s * STAGE;
        #pragma unroll
        for (int i = 0; i < 2; i++) {
            int idx = tid + (i << 8);
            int r = idx >> 2, c = (idx & 3) << 3;
            cp_async16(st + r * PADR + c, Abase + (long)r * D_MODEL + k0 + c);
        }
        cp_commit();
    };

    float4 breg[4];
    const int br = tid >> 1, bc16 = (tid & 1) << 4;
    auto ldgB = [&](int k0) {
        const float4* bp = reinterpret_cast<const float4*>(
            Bf + (long)(n0 + br) * D_MODEL + k0 + bc16);
        breg[0] = bp[0]; breg[1] = bp[1]; breg[2] = bp[2]; breg[3] = bp[3];
    };
    auto stsB = [&](int s) {
        __half* Bh = smh + s * STAGE + 128 * PADR + br * PADR + bc16;
        #pragma unroll
        for (int q = 0; q < 4; q++) {
            __half2 p0 = __floats2half2_rn(breg[q].x, breg[q].y);
            __half2 p1 = __floats2half2_rn(breg[q].z, breg[q].w);
            uint2 v;
            v.x = *reinterpret_cast<unsigned*>(&p0);
            v.y = *reinterpret_cast<unsigned*>(&p1);
            *reinterpret_cast<uint2*>(Bh + q * 4) = v;
        }
    };

    const int nk = D_MODEL / 32;
    ldgB(0);
    load_tileA(0, 0);
    stsB(0);

    const int arow = wm * 32 + (lane & 15);
    const int acol = (lane >> 4) << 3;
    const int brow = wn * 64 + ((lane >> 4) << 3) + (lane & 7);
    const int bcol = ((lane >> 3) & 1) << 3;

    for (int kt = 0; kt < nk; kt++) {
        const bool pf = (kt + 1 < nk);
        if (pf) {
            ldgB((kt + 1) << 5);
            load_tileA((kt + 1) & 1, (kt + 1) << 5);
            cp_wait<1>();
        } else {
            cp_wait<0>();
        }
        __syncthreads();

        const __half* Ap = smh + (kt & 1) * STAGE;
        const __half* Bp = Ap + 128 * PADR;

        #pragma unroll
        for (int kk = 0; kk < 2; kk++) {
            unsigned a[2][4], b[4][4];
            #pragma unroll
            for (int mt = 0; mt < 2; mt++)
                ldsm_x4(a[mt], Ap + (long)(arow + mt * 16) * PADR + kk * 16 + acol);
            #pragma unroll
            for (int p = 0; p < 4; p++)
                ldsm_x4(b[p], Bp + (long)(brow + p * 16) * PADR + kk * 16 + bcol);
            #pragma unroll
            for (int mt = 0; mt < 2; mt++)
                #pragma unroll
                for (int nt = 0; nt < 8; nt++)
                    mma_fp16(acc[mt][nt], a[mt], &b[nt >> 1][(nt & 1) << 1]);
        }
        if (pf) stsB((kt + 1) & 1);
        __syncthreads();
    }

    #pragma unroll
    for (int mt = 0; mt < 2; mt++) {
        int r = m0 + wm * 32 + mt * 16 + gid;
        #pragma unroll
        for (int nt = 0; nt < 8; nt++) {
            int cc = n0 + wn * 64 + nt * 8 + tig * 2;
            *reinterpret_cast<float2*>(C + (long)r * VOCAB + cc) =
                make_float2(acc[mt][nt][0], acc[mt][nt][1]);
            *reinterpret_cast<float2*>(C + (long)(r + 8) * VOCAB + cc) =
                make_float2(acc[mt][nt][2], acc[mt][nt][3]);
        }
    }
}

// -------------------- merged conversions -------------------------------------
__device__ __forceinline__ void conv_seg(const float* src, __nv_bfloat16* dst,
                                         long planeStride, int n8) {
    for (int i = blockIdx.x * blockDim.x + threadIdx.x; i < n8; i += gridDim.x * blockDim.x) {
        float4 a = reinterpret_cast<const float4*>(src)[2 * i];
        float4 b = reinterpret_cast<const float4*>(src)[2 * i + 1];
        uint2 h0, l0, h1, l1;
        split4(a, h0, l0); split4(b, h1, l1);
        uint4 hv; hv.x = h0.x; hv.y = h0.y; hv.z = h1.x; hv.w = h1.y;
        uint4 lv; lv.x = l0.x; lv.y = l0.y; lv.z = l1.x; lv.w = l1.y;
        *reinterpret_cast<uint4*>(dst + ((long)i << 3)) = hv;
        *reinterpret_cast<uint4*>(dst + planeStride + ((long)i << 3)) = lv;
    }
}
__device__ __forceinline__ void conv_seg_il(const float* src, __nv_bfloat16* dst,
                                            int ro, long planeStride, int nRows) {
    int total = nRows * 80;
    for (int i = blockIdx.x * blockDim.x + threadIdx.x; i < total; i += gridDim.x * blockDim.x) {
        int row = i / 80, c8 = i % 80;
        const float4* s = reinterpret_cast<const float4*>(src + (long)row * 640 + c8 * 8);
        float4 a = s[0], b = s[1];
        uint2 h0, l0, h1, l1;
        split4(a, h0, l0); split4(b, h1, l1);
        uint4 hv; hv.x = h0.x; hv.y = h0.y; hv.z = h1.x; hv.w = h1.y;
        uint4 lv; lv.x = l0.x; lv.y = l0.y; lv.z = l1.x; lv.w = l1.y;
        __nv_bfloat16* d = dst + (long)(2 * row + ro) * 640 + c8 * 8;
        *reinterpret_cast<uint4*>(d) = hv;
        *reinterpret_cast<uint4*>(d + planeStride) = lv;
    }
}
__global__ void conv_all_a(const float* __restrict__ wq, const float* __restrict__ wk,
                           const float* __restrict__ wv, __nv_bfloat16* __restrict__ wqkv2) {
    const long pQKV = (long)1536 * 640;
    int l = blockIdx.z;
    __nv_bfloat16* dst = wqkv2 + (long)l * 2 * pQKV;
    if (blockIdx.y == 0)
        conv_seg(wq + (long)l * 1024 * 640, dst,               pQKV, 1024 * 640 / 8);
    else if (blockIdx.y == 1)
        conv_seg(wk + (long)l *  256 * 640, dst + 1024L * 640, pQKV,  256 * 640 / 8);
    else
        conv_seg(wv + (long)l *  256 * 640, dst + 1280L * 640, pQKV,  256 * 640 / 8);
}
__global__ void conv_all_b(const float* __restrict__ wo, const float* __restrict__ wg,
                           const float* __restrict__ wu, const float* __restrict__ wd,
                           __nv_bfloat16* __restrict__ wo2, __nv_bfloat16* __restrict__ wgu2,
                           __nv_bfloat16* __restrict__ wd2) {
    const long pWO = (long)640 * 1024, pWGU = (long)4096 * 640, pWD = (long)640 * 2048;
    int l = blockIdx.z;
    if (blockIdx.y == 0)
        conv_seg(wo + (long)l * 640 * 1024, wo2 + (long)l * 2 * pWO, pWO, 640 * 1024 / 8);
    else if (blockIdx.y == 1)
        conv_seg_il(wg + (long)l * 2048 * 640, wgu2 + (long)l * 2 * pWGU, 0, pWGU, 2048);
    else if (blockIdx.y == 2)
        conv_seg_il(wu + (long)l * 2048 * 640, wgu2 + (long)l * 2 * pWGU, 1, pWGU, 2048);
    else
        conv_seg(wd + (long)l * 640 * 2048, wd2 + (long)l * 2 * pWD, pWD, 640 * 2048 / 8);
}

// -------------------- rope tables -------------------------------------------
__global__ void rope_table_kernel() {
    int t = blockIdx.x, b = blockIdx.y, d = threadIdx.x;
    float base = b ? 1000000.0f : 10000.0f;
    float invf = powf(base, -((float)d) / 128.0f);
    float s, c;
    sincosf((float)t * invf, &s, &c);
    long idx = ((long)b * SEQ + t) * 128 + d;
    g_ropec[idx] = c;
    g_ropes[idx] = s;
}

// -------------------- elementwise / norm kernels -----------------------------
__global__ void embed_kernel(const int* __restrict__ ids, const float* __restrict__ emb,
                             float* __restrict__ x) {
    int t = blockIdx.x;
    long id = (long)ids[t];
    for (int d = threadIdx.x; d < D_MODEL; d += blockDim.x)
        x[(long)t * D_MODEL + d] = emb[id * D_MODEL + d] * EMB_SCALE;
}

__global__ void rmsnorm_split_kernel(const float* __restrict__ x, const float* __restrict__ w,
                                     __nv_bfloat16* __restrict__ o2, long plane) {
    int t = blockIdx.x;
    const float* row = x + (long)t * D_MODEL;
    float ss = 0.0f;
    for (int d = threadIdx.x; d < D_MODEL; d += blockDim.x) { float v = row[d]; ss += v * v; }
    ss = block_reduce_sum(ss);
    float scale = rsqrtf(ss / (float)D_MODEL + 1e-6f);
    for (int d = threadIdx.x; d < D_MODEL; d += blockDim.x)
        store_split_plane(o2 + (long)t * D_MODEL + d, plane, row[d] * scale * (1.0f + w[d]));
}

__global__ void rmsadd_norm_split(float* __restrict__ x, const float* __restrict__ tmp,
                                  long tmpSlice,
                                  const float* __restrict__ wa, const float* __restrict__ wn,
                                  __nv_bfloat16* __restrict__ o2, long plane,
                                  __half* __restrict__ oh) {
    int t = blockIdx.x, tid = threadIdx.x;
    float* xr = x + (long)t * D_MODEL;
    const float* tr  = tmp + (long)t * D_MODEL;
    float tv[3];
    float ss = 0.0f;
    #pragma unroll
    for (int i = 0; i < 3; i++) {
        int d = tid + (i << 8);
        if (d < D_MODEL) {
            tv[i] = tr[d] + tr[d + tmpSlice] + tr[d + 2 * tmpSlice];
            ss += tv[i] * tv[i];
        }
    }
    ss = block_reduce_sum(ss);
    float s1 = rsqrtf(ss / (float)D_MODEL + 1e-6f);
    float xv[3];
    ss = 0.0f;
    #pragma unroll
    for (int i = 0; i < 3; i++) {
        int d = tid + (i << 8);
        if (d < D_MODEL) {
            xv[i] = xr[d] + tv[i] * s1 * (1.0f + wa[d]);
            xr[d] = xv[i];
            ss += xv[i] * xv[i];
        }
    }
    ss = block_reduce_sum(ss);
    float s2 = rsqrtf(ss / (float)D_MODEL + 1e-6f);
    #pragma unroll
    for (int i = 0; i < 3; i++) {
        int d = tid + (i << 8);
        if (d < D_MODEL) {
            float v = xv[i] * s2 * (1.0f + wn[d]);
            store_split_plane(o2 + (long)t * D_MODEL + d, plane, v);
            if (oh) oh[(long)t * D_MODEL + d] = __float2half(v);
        }
    }
}

__global__ void qknorm_rope_fused(const float* __restrict__ qkv, long dup,
                                  const float* __restrict__ qw, const float* __restrict__ kw,
                                  __nv_bfloat16* __restrict__ q2, __nv_bfloat16* __restrict__ k2,
                                  long pQ, long pK, int bsel) {
    int t = blockIdx.x, h = blockIdx.y, d = threadIdx.x;
    const float* row;
    __nv_bfloat16* orow;
    const float* w;
    long plane;
    if (h < NHEADS) {
        row = qkv + (long)t * 1536 + h * HEADDIM;
        orow = q2 + (long)t * 1024 + h * HEADDIM;
        w = qw; plane = pQ;
    } else {
        row = qkv + (long)t * 1536 + 1024;
        orow = k2 + (long)t * 256;
        w = kw; plane = pK;
    }
    float v1 = row[d] + row[d + dup] + row[d + 2 * dup];
    float v2 = row[d + 128] + row[d + 128 + dup] + row[d + 128 + 2 * dup];
    float ss = block_reduce_sum(v1 * v1 + v2 * v2);
    float scale = rsqrtf(ss / (float)HEADDIM + 1e-6f);
    float q1 = v1 * scale * (1.0f + w[d]);
    float q2v = v2 * scale * (1.0f + w[d + 128]);
    long ridx = ((long)bsel * SEQ + t) * 128 + d;
    float c = g_ropec[ridx], s = g_ropes[ridx];
    store_split_plane(orow + d,       plane, q1 * c - q2v * s);
    store_split_plane(orow + d + 128, plane, q1 * s + q2v * c);
}

__global__ void transpose_split(const float* __restrict__ in, int rs, long dup,
                                __nv_bfloat16* __restrict__ out, long plane) {
    __shared__ float tile[32][33];
    int r0 = blockIdx.y << 5, c0 = blockIdx.x << 5;
    int x = threadIdx.x, y = threadIdx.y;
    #pragma unroll
    for (int i = 0; i < 32; i += 8) {
        long idx = (long)(r0 + y + i) * rs + c0 + x;
        tile[y + i][x] = in[idx] + in[idx + dup] + in[idx + 2 * dup];
    }
    __syncthreads();
    #pragma unroll
    for (int i = 0; i < 32; i += 8)
        store_split_plane(out + (long)(c0 + y + i) * SEQ + r0 + x, plane, tile[x][y + i]);
}

__global__ void softmax_split_kernel(const float* __restrict__ S,
                                     __nv_bfloat16* __restrict__ P, int win) {
    __shared__ float buf[1024];
    int i = blockIdx.x, h = blockIdx.y;
    const float* row = S + ((long)h << 20) + ((long)i << 10);
    __nv_bfloat16* prow = P + (long)h * (2 << 20) + ((long)i << 10);
    const long plane = 1 << 20;
    int lo = i - win + 1; if (lo < 0) lo = 0;
    int m0 = i & ~127;
    int jlo = m0 - win + 1; if (jlo < 0) jlo = 0; jlo &= ~31;
    int jhi = m0 + 128; if (jhi > SEQ) jhi = SEQ;

    float mx = -3.0e38f;
    for (int j = lo + threadIdx.x; j <= i; j += blockDim.x) {
        float v = row[j] * 0.0625f;
        buf[j - jlo] = v;
        mx = fmaxf(mx, v);
    }
    mx = block_reduce_max(mx);
    float sum = 0.0f;
    for (int j = lo + threadIdx.x; j <= i; j += blockDim.x) {
        float e = __expf(buf[j - jlo] - mx);
        buf[j - jlo] = e;
        sum += e;
    }
    sum = block_reduce_sum(sum);
    float inv = 1.0f / sum;
    for (int j = jlo + threadIdx.x; j < jhi; j += blockDim.x) {
        float v = (j >= lo && j <= i) ? buf[j - jlo] * inv : 0.0f;
        store_split_plane(prow + j, plane, v);
    }
}

// -------------------- launch ------------------------------------------------
extern "C" void kernel_launch(void* const* d_in, const int* in_sizes, int n_in,
                              void* d_out, int out_size) {
    const int*   input_ids = (const int*)  d_in[0];
    const float* embed     = (const float*)d_in[1];
    const float* ln_in     = (const float*)d_in[2];
    const float* wq        = (const float*)d_in[3];
    const float* wk        = (const float*)d_in[4];
    const float* wv        = (const float*)d_in[5];
    const float* qnw       = (const float*)d_in[6];
    const float* knw       = (const float*)d_in[7];
    const float* wo        = (const float*)d_in[8];
    const float* ln_pa     = (const float*)d_in[9];
    const float* ln_pf     = (const float*)d_in[10];
    const float* wg        = (const float*)d_in[11];
    const float* wu        = (const float*)d_in[12];
    const float* wd        = (const float*)d_in[13];
    const float* ln_ff     = (const float*)d_in[14];
    const float* norm_f    = (const float*)d_in[15];
    float* out = (float*)d_out;

    const int SMEM128 = 3 * (256 + 128) * PADR * 2;   // BM=128 stages
    const int SMEM64B = 3 * (128 + 128) * PADR * 2;   // BM=64 stages
    const int SMEMLMH = 2 * 256 * PADR * 2;
    cudaFuncSetAttribute(gemm3<0, 128>, cudaFuncAttributeMaxDynamicSharedMemorySize, SMEM128);
    cudaFuncSetAttribute(gemm3<0, 64>,  cudaFuncAttributeMaxDynamicSharedMemorySize, SMEM64B);
    cudaFuncSetAttribute(gemm3<1, 64>,  cudaFuncAttributeMaxDynamicSharedMemorySize, SMEM64B);
    cudaFuncSetAttribute(gemm3<2, 128>, cudaFuncAttributeMaxDynamicSharedMemorySize, SMEM128);
    cudaFuncSetAttribute(lmhead_h,      cudaFuncAttributeMaxDynamicSharedMemorySize, SMEMLMH);

    float *x, *tmpd, *qkv, *sc;
    __nv_bfloat16 *xn2, *q2, *k2, *vt2, *p2, *ctx2, *ga2;
    __nv_bfloat16 *wqkv2, *wo2, *wgu2, *wd2;
    __half *xnh;
    cudaGetSymbolAddress((void**)&x,     g_x);
    cudaGetSymbolAddress((void**)&tmpd,  g_tmpd);
    cudaGetSymbolAddress((void**)&xn2,   g_xn2);
    cudaGetSymbolAddress((void**)&xnh,   g_xnh);
    cudaGetSymbolAddress((void**)&qkv,   g_qkv);
    cudaGetSymbolAddress((void**)&q2,    g_q2);
    cudaGetSymbolAddress((void**)&k2,    g_k2);
    cudaGetSymbolAddress((void**)&vt2,   g_vt2);
    cudaGetSymbolAddress((void**)&sc,    g_sc);
    cudaGetSymbolAddress((void**)&p2,    g_p2);
    cudaGetSymbolAddress((void**)&ctx2,  g_ctx2);
    cudaGetSymbolAddress((void**)&ga2,   g_ga2);
    cudaGetSymbolAddress((void**)&wqkv2, g_wqkv2);
    cudaGetSymbolAddress((void**)&wo2,   g_wo2);
    cudaGetSymbolAddress((void**)&wgu2,  g_wgu2);
    cudaGetSymbolAddress((void**)&wd2,   g_wd2);

    const long pXN  = (long)SEQ * D_MODEL;
    const long pQ   = (long)SEQ * 1024;
    const long pK   = (long)SEQ * 256;
    const long pVT  = (long)HEADDIM * SEQ;
    const long pGA  = (long)SEQ * DFF;
    const long QKV_SLICE = (long)SEQ * 1536;

    embed_kernel<<<SEQ, 256>>>(input_ids, embed, x);
    rope_table_kernel<<<dim3(SEQ, 2), 128>>>();
    conv_all_a<<<dim3(320, 3, NLAYERS), 256>>>(wq, wk, wv, wqkv2);
    conv_all_b<<<dim3(640, 4, NLAYERS), 256>>>(wo, wg, wu, wd, wo2, wgu2, wd2);
    rmsnorm_split_kernel<<<SEQ, 256>>>(x, ln_in, xn2, pXN);

    const long pQKV = (long)1536 * 640;
    const long pWO  = (long)640 * 1024;
    const long pWGU = (long)4096 * 640;
    const long pWD  = (long)640 * 2048;

    for (int l = 0; l < NLAYERS; l++) {
        const float* qnw_l   = qnw + l * HEADDIM;
        const float* knw_l   = knw + l * HEADDIM;
        const float* ln_pa_l = ln_pa + l * D_MODEL;
        const float* ln_pf_l = ln_pf + l * D_MODEL;
        const float* ln_ff_l = ln_ff + l * D_MODEL;
        const float* next_w  = (l + 1 < NLAYERS) ? (ln_in + (l + 1) * D_MODEL) : norm_f;
        const __nv_bfloat16* wqkv_l = wqkv2 + (long)l * 2 * pQKV;
        const __nv_bfloat16* wo_l   = wo2   + (long)l * 2 * pWO;
        const __nv_bfloat16* wgu_l  = wgu2  + (long)l * 2 * pWGU;
        const __nv_bfloat16* wd_l   = wd2   + (long)l * 2 * pWD;

        bool is_global = ((l + 1) % 6) == 0;
        int   win  = is_global ? 32768 : 512;
        int   bsel = is_global ? 1 : 0;

        // qkv: split-K x3 -> 576 CTAs
        gemm3<0, 128><<<dim3(24, 8, 3), 256, SMEM128>>>(xn2, wqkv_l, qkv, nullptr,
            640, 640, 640, pXN, pQKV, 1536, 0, 0, 0, QKV_SLICE, -1, -1, 224);
        qknorm_rope_fused<<<dim3(SEQ, NHEADS + 1), 128>>>(qkv, QKV_SLICE, qnw_l, knw_l,
            q2, k2, pQ, pK, bsel);
        transpose_split<<<dim3(8, 32), dim3(32, 8)>>>(qkv + 1280, 1536, QKV_SLICE, vt2, pVT);
        // scores: BM=64 (3 CTAs/SM) with banded skip
        gemm3<0, 64><<<dim3(16, 16, NHEADS), 256, SMEM64B>>>(q2, k2, sc, nullptr,
            256, 1024, 256, pQ, pK, 1024, 0, 256, 0, (long)1 << 20, win, -1, 0);
        softmax_split_kernel<<<dim3(SEQ, NHEADS), 256>>>(sc, p2, win);
        // ctx: BM=64 (3 CTAs/SM), band-limited k
        gemm3<1, 64><<<dim3(4, 16, NHEADS), 256, SMEM64B>>>(p2, vt2, nullptr, ctx2,
            1024, 1024, 1024, pQ, pVT, 1024, pQ, (long)2 << 20, 0, 256, -1, win, 0);
        // wo: split-K x3 -> 240 CTAs
        gemm3<0, 128><<<dim3(10, 8, 3), 256, SMEM128>>>(ctx2, wo_l, tmpd, nullptr,
            1024, 1024, 1024, pQ, pWO, D_MODEL, 0, 0, 0, pXN, -1, -1, 352);
        rmsadd_norm_split<<<SEQ, 256>>>(x, tmpd, pXN, ln_pa_l, ln_pf_l, xn2, pXN, nullptr);
        gemm3<2, 128><<<dim3(64, 8), 256, SMEM128>>>(xn2, wgu_l, nullptr, ga2,
            640, 640, 640, pXN, pWGU, DFF, pGA, 0, 0, 0, -1, -1, 0);
        // wd: split-K x3 -> 240 CTAs
        gemm3<0, 128><<<dim3(10, 8, 3), 256, SMEM128>>>(ga2, wd_l, tmpd, nullptr,
            2048, 2048, 2048, pGA, pWD, D_MODEL, 0, 0, 0, pXN, -1, -1, 704);
        rmsadd_norm_split<<<SEQ, 256>>>(x, tmpd, pXN, ln_ff_l, next_w, xn2, pXN,
            (l + 1 == NLAYERS) ? xnh : nullptr);
    }

    lmhead_h<<<dim3(8, VOCAB / 128), 256, SMEMLMH>>>(xnh, embed, out);
    (void)in_sizes; (void)n_in; (void)out_size;
}